// round 8
// baseline (speedup 1.0000x reference)
#include <cuda_runtime.h>

#define BB 64
#define SS 512
#define II 1024
#define HH 1024
#define NG 4096          // 4*H
#define MMR (BB*SS)      // 32768
#define NCTA 128
#define PTHR 512

// ---------------- device scratch (no allocs allowed) ----------------
__device__ __align__(16) float g_Up[(size_t)NG * II];       // U_all^T  [n][k], tf32-rounded
__device__ __align__(16) float g_Wp[(size_t)NG * HH];       // W_all^T  [n][k], tf32-rounded
__device__ __align__(16) float g_xp[(size_t)MMR * NG];      // x_proj   [(s*64+b)][4H]
// h in a-fragment order: [buf][kk8(128)][row(64)][q(4) as float2 {k=8kk8+q, k=8kk8+q+4}]
__device__ __align__(16) float g_hf[2][64 * 1024];
// dataflow flags, 128B-strided (distinct L2 lines per CTA)
__device__ unsigned g_wflag[NCTA * 32];   // CTA j has written h_{wflag[j]}
__device__ unsigned g_rflag[NCTA * 32];   // CTA i has finished reading h_{rflag[i]-1}

// ---------------- helpers ----------------
__device__ __forceinline__ float tf32r(float f) {
    unsigned u;
    asm("cvt.rna.tf32.f32 %0, %1;" : "=r"(u) : "f"(f));
    return __uint_as_float(u);
}

__device__ __forceinline__ void mma8(float* d, const unsigned* a, unsigned b0, unsigned b1) {
    asm volatile(
        "mma.sync.aligned.m16n8k8.row.col.f32.tf32.tf32.f32 "
        "{%0,%1,%2,%3}, {%4,%5,%6,%7}, {%8,%9}, {%0,%1,%2,%3};"
        : "+f"(d[0]), "+f"(d[1]), "+f"(d[2]), "+f"(d[3])
        : "r"(a[0]), "r"(a[1]), "r"(a[2]), "r"(a[3]), "r"(b0), "r"(b1));
}

__device__ __forceinline__ float sigmf(float x) { return 1.f / (1.f + __expf(-x)); }

__device__ __forceinline__ unsigned ld_acq(const unsigned* p) {
    unsigned v;
    asm volatile("ld.acquire.gpu.global.u32 %0, [%1];" : "=r"(v) : "l"(p) : "memory");
    return v;
}

__device__ __forceinline__ void st_rel(unsigned* p, unsigned v) {
    asm volatile("st.release.gpu.global.u32 [%0], %1;" :: "l"(p), "r"(v) : "memory");
}

// ---------------- pack: build K-major tf32 U_all^T / W_all^T ----------------
__global__ void pack_kernel(
    const float* __restrict__ Uf, const float* __restrict__ Ui,
    const float* __restrict__ Uc, const float* __restrict__ Uo,
    const float* __restrict__ Wf, const float* __restrict__ Wi,
    const float* __restrict__ Wc, const float* __restrict__ Wo)
{
    __shared__ float t[32][33];
    int z = blockIdx.z;
    int g = z & 3;
    const float* src;
    float* dst;
    if (z < 4) { src = (g == 0) ? Uf : (g == 1) ? Ui : (g == 2) ? Uc : Uo; dst = g_Up; }
    else       { src = (g == 0) ? Wf : (g == 1) ? Wi : (g == 2) ? Wc : Wo; dst = g_Wp; }
    int n0 = blockIdx.x * 32, k0 = blockIdx.y * 32;
    int tx = threadIdx.x, ty = threadIdx.y;   // 32 x 8
    #pragma unroll
    for (int i = 0; i < 4; i++) {
        int kr = ty + i * 8;
        t[kr][tx] = src[(size_t)(k0 + kr) * HH + n0 + tx];
    }
    __syncthreads();
    #pragma unroll
    for (int i = 0; i < 4; i++) {
        int nr = ty + i * 8;
        dst[(size_t)(g * HH + n0 + nr) * II + k0 + tx] = tf32r(t[tx][nr]);
    }
}

__global__ void init_kernel() {
    int i = blockIdx.x * blockDim.x + threadIdx.x;
    if (i < 64 * 1024) g_hf[0][i] = 0.f;
    if (i < NCTA * 32) { g_wflag[i] = 0u; g_rflag[i] = 0u; }
}

// ---------------- phase 1: x_proj = x @ U_all + b ----------------
__global__ __launch_bounds__(256, 2) void xproj_kernel(
    const float* __restrict__ x,
    const float* __restrict__ bf, const float* __restrict__ bi,
    const float* __restrict__ bc, const float* __restrict__ bo)
{
    __shared__ float As[2][128][20];
    __shared__ float Bs[2][128][20];
    const int tid = threadIdx.x, lane = tid & 31, warp = tid >> 5;
    const int wm = warp >> 1, wn = warp & 1;
    const int gq = lane >> 2, tq = lane & 3;
    const int m0 = blockIdx.y * 128, n0 = blockIdx.x * 128;

    float acc[2][8][4];
    #pragma unroll
    for (int a = 0; a < 2; a++)
        #pragma unroll
        for (int b = 0; b < 8; b++)
            #pragma unroll
            for (int c = 0; c < 4; c++) acc[a][b][c] = 0.f;

    float4 ra[2], rb[2];
    #pragma unroll
    for (int it = 0; it < 2; it++) {
        int idx = tid + it * 256, row = idx >> 2, kq = idx & 3;
        ra[it] = *(const float4*)(x    + (size_t)(m0 + row) * II + kq * 4);
        rb[it] = *(const float4*)(g_Up + (size_t)(n0 + row) * II + kq * 4);
    }
    #pragma unroll
    for (int it = 0; it < 2; it++) {
        int idx = tid + it * 256, row = idx >> 2, kq = idx & 3;
        As[0][row][kq*4+0] = tf32r(ra[it].x); As[0][row][kq*4+1] = tf32r(ra[it].y);
        As[0][row][kq*4+2] = tf32r(ra[it].z); As[0][row][kq*4+3] = tf32r(ra[it].w);
        Bs[0][row][kq*4+0] = rb[it].x; Bs[0][row][kq*4+1] = rb[it].y;
        Bs[0][row][kq*4+2] = rb[it].z; Bs[0][row][kq*4+3] = rb[it].w;
    }
    __syncthreads();

    const int NK = II / 16;
    for (int kc = 0; kc < NK; kc++) {
        int buf = kc & 1;
        if (kc + 1 < NK) {
            int k0 = (kc + 1) * 16;
            #pragma unroll
            for (int it = 0; it < 2; it++) {
                int idx = tid + it * 256, row = idx >> 2, kq = idx & 3;
                ra[it] = *(const float4*)(x    + (size_t)(m0 + row) * II + k0 + kq * 4);
                rb[it] = *(const float4*)(g_Up + (size_t)(n0 + row) * II + k0 + kq * 4);
            }
        }
        #pragma unroll
        for (int kk = 0; kk < 16; kk += 8) {
            unsigned a[2][4], b[8][2];
            #pragma unroll
            for (int mf = 0; mf < 2; mf++) {
                int r = wm * 32 + mf * 16 + gq;
                a[mf][0] = __float_as_uint(As[buf][r    ][kk + tq]);
                a[mf][1] = __float_as_uint(As[buf][r + 8][kk + tq]);
                a[mf][2] = __float_as_uint(As[buf][r    ][kk + tq + 4]);
                a[mf][3] = __float_as_uint(As[buf][r + 8][kk + tq + 4]);
            }
            #pragma unroll
            for (int nf = 0; nf < 8; nf++) {
                int c = wn * 64 + nf * 8 + gq;
                b[nf][0] = __float_as_uint(Bs[buf][c][kk + tq]);
                b[nf][1] = __float_as_uint(Bs[buf][c][kk + tq + 4]);
            }
            #pragma unroll
            for (int mf = 0; mf < 2; mf++)
                #pragma unroll
                for (int nf = 0; nf < 8; nf++)
                    mma8(acc[mf][nf], a[mf], b[nf][0], b[nf][1]);
        }
        if (kc + 1 < NK) {
            int nb = buf ^ 1;
            #pragma unroll
            for (int it = 0; it < 2; it++) {
                int idx = tid + it * 256, row = idx >> 2, kq = idx & 3;
                As[nb][row][kq*4+0] = tf32r(ra[it].x); As[nb][row][kq*4+1] = tf32r(ra[it].y);
                As[nb][row][kq*4+2] = tf32r(ra[it].z); As[nb][row][kq*4+3] = tf32r(ra[it].w);
                Bs[nb][row][kq*4+0] = rb[it].x; Bs[nb][row][kq*4+1] = rb[it].y;
                Bs[nb][row][kq*4+2] = rb[it].z; Bs[nb][row][kq*4+3] = rb[it].w;
            }
        }
        __syncthreads();
    }

    #pragma unroll
    for (int mf = 0; mf < 2; mf++) {
        int mr = m0 + wm * 32 + mf * 16 + gq;
        int m1 = mr + 8;
        size_t r0 = (size_t)(((mr & 511) << 6) | (mr >> 9)) * NG;
        size_t r1 = (size_t)(((m1 & 511) << 6) | (m1 >> 9)) * NG;
        #pragma unroll
        for (int nf = 0; nf < 8; nf++) {
            int c0 = n0 + wn * 64 + nf * 8 + 2 * tq;
            int gate = c0 >> 10;
            const float* bp = (gate == 0) ? bf : (gate == 1) ? bi : (gate == 2) ? bc : bo;
            float bv0 = bp[c0 & 1023], bv1 = bp[(c0 + 1) & 1023];
            g_xp[r0 + c0    ] = acc[mf][nf][0] + bv0;
            g_xp[r0 + c0 + 1] = acc[mf][nf][1] + bv1;
            g_xp[r1 + c0    ] = acc[mf][nf][2] + bv0;
            g_xp[r1 + c0 + 1] = acc[mf][nf][3] + bv1;
        }
    }
}

// ---------------- persistent recurrence kernel (dataflow-synced) ----------------
// 128 CTAs x 512 thr (16 warps = 2 m-slabs x 8 K-splits). CTA j owns hidden cols
// [8j,8j+8) -> 32 gate cols, and PRODUCES h-slice kk8=j. Consumers gate per-warp
// on the 16 producer wflags of their K-range; producers gate h-stores on rflags.
#define SM_W_BYTES   131072                    // 8192 float4
#define RED_STRIDE   36                        // floats per (warp,lane) slot (=9 float4)
#define SM_RED_BYTES (PTHR * RED_STRIDE * 4)   // 73728
#define SM_TOTAL     (SM_W_BYTES + SM_RED_BYTES)

__global__ __launch_bounds__(PTHR, 1) void lstm_persistent(
    float* __restrict__ out, float* __restrict__ out_hs)
{
    extern __shared__ __align__(16) unsigned char sm_raw[];
    float4* Wsm4 = (float4*)sm_raw;                          // [kk8][gp2][gq8][tq4]
    float2* Wsm2 = (float2*)sm_raw;
    float4* red4 = (float4*)(sm_raw + SM_W_BYTES);           // [(w*32+lane)][9] float4

    const int tid = threadIdx.x;
    const int lane = tid & 31, w = tid >> 5;
    const int wm = w & 1, kh = w >> 1;        // 2 m-slabs x 8 K-splits
    const int gq = lane >> 2, tq = lane & 3;
    const int j = blockIdx.x;

    // ---- one-time: load W slice into gate-paired fragment layout ----
    #pragma unroll
    for (int t = 0; t < 8; t++) {
        int job = tid + t * PTHR;        // 4096 jobs = 32 n x 128 kk8
        int n = job >> 7;
        int kk8 = job & 127;
        int g = n >> 3, gn = n & 7;
        int gp = g >> 1, gh = g & 1;
        const float* src = g_Wp + (size_t)(g * 1024 + j * 8 + gn) * HH + kk8 * 8;
        float4 lo = *(const float4*)src;
        float4 hi = *(const float4*)(src + 4);
        int base2 = (((kk8 * 2 + gp) * 8 + gn) * 4) * 2;
        Wsm2[base2 + 0 * 2 + gh] = make_float2(lo.x, hi.x);
        Wsm2[base2 + 1 * 2 + gh] = make_float2(lo.y, hi.y);
        Wsm2[base2 + 2 * 2 + gh] = make_float2(lo.z, hi.z);
        Wsm2[base2 + 3 * 2 + gh] = make_float2(lo.w, hi.w);
    }
    __syncthreads();

    // ---- per-thread epilogue mapping (one (row, cc) output per thread) ----
    const int rrow = tid >> 3, cc = tid & 7;
    const int r_wm = rrow >> 5, r_mt = (rrow >> 4) & 1;
    const int r_p  = ((rrow >> 3) & 1) * 2 + (cc & 1);
    const int r_lane = (rrow & 7) * 4 + (cc >> 1);
    const int red_f4 = r_lane * 9 + r_mt * 4 + r_p;          // + (kh2*2+r_wm)*32*9
    const int colg = j * 8 + cc;
    const int hf_idx = (j * 64 + rrow) * 8 + (cc & 3) * 2 + (cc >> 2);

    float creg = 0.f;

    const int kbase = kh * 16;                 // this warp's kk8 range (16 slices)
    const int arow = wm * 32 + gq;             // mt0 a-frag row

    // prefetch xp for step 0
    float xr[4];
    #pragma unroll
    for (int g = 0; g < 4; g++)
        xr[g] = __ldg(g_xp + (size_t)rrow * NG + g * 1024 + colg);

    for (int s = 0; s < SS; s++) {
        const float2* __restrict__ hb = (const float2*)g_hf[s & 1];
        float*        __restrict__ hw = g_hf[(s + 1) & 1];

        // per-warp consumer gate: producers of my 16 slices have written h_s
        if (s > 0) {
            if (lane < 16) {
                const unsigned* fp = g_wflag + (kbase + lane) * 32;
                while (ld_acq(fp) < (unsigned)s) { }
            }
            __syncwarp();
        }

        float acc[2][4][4];
        #pragma unroll
        for (int mt = 0; mt < 2; mt++)
            #pragma unroll
            for (int g = 0; g < 4; g++)
                #pragma unroll
                for (int p = 0; p < 4; p++) acc[mt][g][p] = 0.f;

        // 4-deep a-fragment prefetch queue: [slot][lo0,hi0,lo1,hi1]
        float2 qA[4][4];
        #pragma unroll
        for (int p = 0; p < 4; p++) {
            int base = ((kbase + p) * 64 + arow) * 4 + tq;
            qA[p][0] = __ldcg(hb + base);
            qA[p][1] = __ldcg(hb + base + 32);    // +8 rows
            qA[p][2] = __ldcg(hb + base + 64);    // +16 rows (mt1)
            qA[p][3] = __ldcg(hb + base + 96);
        }

        #pragma unroll 4
        for (int i = 0; i < 16; i++) {
            int sl = i & 3;
            float2 l0 = qA[sl][0], h0 = qA[sl][1], l1 = qA[sl][2], h1 = qA[sl][3];
            if (i < 12) {
                int base = ((kbase + i + 4) * 64 + arow) * 4 + tq;
                qA[sl][0] = __ldcg(hb + base);
                qA[sl][1] = __ldcg(hb + base + 32);
                qA[sl][2] = __ldcg(hb + base + 64);
                qA[sl][3] = __ldcg(hb + base + 96);
            }
            unsigned a0[4] = { __float_as_uint(l0.x), __float_as_uint(h0.x),
                               __float_as_uint(l0.y), __float_as_uint(h0.y) };
            unsigned a1[4] = { __float_as_uint(l1.x), __float_as_uint(h1.x),
                               __float_as_uint(l1.y), __float_as_uint(h1.y) };
            int kk8 = kbase + i;
            float4 b01 = Wsm4[((kk8 * 2 + 0) * 8 + gq) * 4 + tq];
            float4 b23 = Wsm4[((kk8 * 2 + 1) * 8 + gq) * 4 + tq];
            mma8(acc[0][0], a0, __float_as_uint(b01.x), __float_as_uint(b01.y));
            mma8(acc[0][1], a0, __float_as_uint(b01.z), __float_as_uint(b01.w));
            mma8(acc[0][2], a0, __float_as_uint(b23.x), __float_as_uint(b23.y));
            mma8(acc[0][3], a0, __float_as_uint(b23.z), __float_as_uint(b23.w));
            mma8(acc[1][0], a1, __float_as_uint(b01.x), __float_as_uint(b01.y));
            mma8(acc[1][1], a1, __float_as_uint(b01.z), __float_as_uint(b01.w));
            mma8(acc[1][2], a1, __float_as_uint(b23.x), __float_as_uint(b23.y));
            mma8(acc[1][3], a1, __float_as_uint(b23.z), __float_as_uint(b23.w));
        }

        // dump partials, p-major so epilogue reads are LDS.128
        {
            float4* dst4 = red4 + (w * 32 + lane) * 9;
            #pragma unroll
            for (int mt = 0; mt < 2; mt++)
                #pragma unroll
                for (int p = 0; p < 4; p++)
                    dst4[mt * 4 + p] = make_float4(acc[mt][0][p], acc[mt][1][p],
                                                   acc[mt][2][p], acc[mt][3][p]);
        }
        __syncthreads();

        // all loads of h_s are consumed -> release read flag
        if (tid == 0) st_rel(g_rflag + j * 32, (unsigned)(s + 1));

        // unified reduction + gate compute (registers only)
        float hn, cn;
        {
            float gs0 = 0.f, gs1 = 0.f, gs2 = 0.f, gs3 = 0.f;
            #pragma unroll
            for (int kh2 = 0; kh2 < 8; kh2++) {
                float4 v = red4[(kh2 * 2 + r_wm) * 32 * 9 + red_f4];
                gs0 += v.x; gs1 += v.y; gs2 += v.z; gs3 += v.w;
            }
            float gf = gs0 + xr[0];
            float gi = gs1 + xr[1];
            float gc = gs2 + xr[2];
            float go = gs3 + xr[3];
            cn = sigmf(gf) * creg + sigmf(gi) * tanhf(gc);
            creg = cn;
            hn = sigmf(go) * tanhf(cn);
        }

        // WAR gate: all CTAs must be done reading h_{s-1} (buffer being overwritten)
        if (w == 0) {
            const unsigned* fp = g_rflag + lane * 32;
            bool ok;
            do {
                unsigned v0 = ld_acq(fp);
                unsigned v1 = ld_acq(fp + 32 * 32);
                unsigned v2 = ld_acq(fp + 64 * 32);
                unsigned v3 = ld_acq(fp + 96 * 32);
                ok = (v0 >= (unsigned)s) && (v1 >= (unsigned)s) &&
                     (v2 >= (unsigned)s) && (v3 >= (unsigned)s);
            } while (!__all_sync(0xffffffffu, ok));
        }
        __syncthreads();

        // publish h_{s+1} slice, then release write flag
        __stcg(hw + hf_idx, tf32r(hn));
        if (s == SS - 1) {
            out[(size_t)rrow * HH + colg] = hn;
            out[(size_t)BB * HH + (size_t)rrow * HH + colg] = cn;
        }
        __syncthreads();
        if (tid == 0) st_rel(g_wflag + j * 32, (unsigned)(s + 1));

        // off the critical path: hidden_seq store + next xp prefetch
        out_hs[((size_t)rrow * SS + s) * HH + colg] = hn;
        if (s + 1 < SS) {
            #pragma unroll
            for (int g = 0; g < 4; g++)
                xr[g] = __ldg(g_xp + (size_t)((s + 1) * 64 + rrow) * NG + g * 1024 + colg);
        }
    }
}

// ---------------- launch ----------------
extern "C" void kernel_launch(void* const* d_in, const int* in_sizes, int n_in,
                              void* d_out, int out_size)
{
    const float* x  = (const float*)d_in[0];
    const float* Uf = (const float*)d_in[1];
    const float* Ui = (const float*)d_in[2];
    const float* Uc = (const float*)d_in[3];
    const float* Uo = (const float*)d_in[4];
    const float* Wf = (const float*)d_in[5];
    const float* Wi = (const float*)d_in[6];
    const float* Wc = (const float*)d_in[7];
    const float* Wo = (const float*)d_in[8];
    const float* bf = (const float*)d_in[9];
    const float* bi = (const float*)d_in[10];
    const float* bc = (const float*)d_in[11];
    const float* bo = (const float*)d_in[12];
    float* out = (float*)d_out;

    static int smem_set = 0;
    if (!smem_set) {
        cudaFuncSetAttribute(lstm_persistent,
                             cudaFuncAttributeMaxDynamicSharedMemorySize, SM_TOTAL);
        smem_set = 1;
    }

    pack_kernel<<<dim3(32, 32, 8), dim3(32, 8)>>>(Uf, Ui, Uc, Uo, Wf, Wi, Wc, Wo);
    init_kernel<<<(64 * 1024 + 255) / 256, 256>>>();
    xproj_kernel<<<dim3(NG / 128, MMR / 128), 256>>>(x, bf, bi, bc, bo);

    float* hs = out + 2 * BB * HH;   // hidden_seq region
    lstm_persistent<<<NCTA, PTHR, SM_TOTAL>>>(out, hs);
}

// round 9
// speedup vs baseline: 1.5098x; 1.5098x over previous
#include <cuda_runtime.h>
#include <cuda_fp16.h>

#define BB 64
#define SS 512
#define II 1024
#define HH 1024
#define NG 4096          // 4*H
#define MMR (BB*SS)      // 32768
#define NCTA 128
#define PTHR 512

// ---------------- device scratch (no allocs allowed) ----------------
__device__ __align__(16) __half g_Uph[(size_t)NG * II];     // U_all^T [n][k], fp16
__device__ __align__(16) __half g_Wph[(size_t)NG * HH];     // W_all^T [n][k], fp16
__device__ __align__(16) float  g_xp[(size_t)MMR * NG];     // x_proj  [(s*64+b)][4H]
// h fp16 in a-fragment order:
// uint2 index ((kk16*64 + row)*4 + tq); .x = halves(k=16kk16+2tq, +1), .y = halves(+8,+9)
__device__ __align__(16) unsigned g_hf[2][32768];
__device__ unsigned g_cnt;                                   // grid barrier arrivals
__device__ unsigned g_gen;                                   // grid barrier generation

// ---------------- helpers ----------------
__device__ __forceinline__ unsigned h2pack(float lo, float hi) {
    unsigned u;
    asm("cvt.rn.f16x2.f32 %0, %1, %2;" : "=r"(u) : "f"(hi), "f"(lo));
    return u;
}

__device__ __forceinline__ void mma16(float* d, const unsigned* a, unsigned b0, unsigned b1) {
    asm volatile(
        "mma.sync.aligned.m16n8k16.row.col.f32.f16.f16.f32 "
        "{%0,%1,%2,%3}, {%4,%5,%6,%7}, {%8,%9}, {%0,%1,%2,%3};"
        : "+f"(d[0]), "+f"(d[1]), "+f"(d[2]), "+f"(d[3])
        : "r"(a[0]), "r"(a[1]), "r"(a[2]), "r"(a[3]), "r"(b0), "r"(b1));
}

__device__ __forceinline__ float sigmf(float x) { return 1.f / (1.f + __expf(-x)); }

__device__ __forceinline__ void st_h_cg(__half* p, __half v) {
    unsigned short s = __half_as_ushort(v);
    asm volatile("st.global.cg.u16 [%0], %1;" :: "l"(p), "h"(s) : "memory");
}

// ---------------- pack: build K-major fp16 U_all^T / W_all^T ----------------
__global__ void pack_kernel(
    const float* __restrict__ Uf, const float* __restrict__ Ui,
    const float* __restrict__ Uc, const float* __restrict__ Uo,
    const float* __restrict__ Wf, const float* __restrict__ Wi,
    const float* __restrict__ Wc, const float* __restrict__ Wo)
{
    __shared__ float t[32][33];
    int z = blockIdx.z;
    int g = z & 3;
    const float* src;
    __half* dst;
    if (z < 4) { src = (g == 0) ? Uf : (g == 1) ? Ui : (g == 2) ? Uc : Uo; dst = g_Uph; }
    else       { src = (g == 0) ? Wf : (g == 1) ? Wi : (g == 2) ? Wc : Wo; dst = g_Wph; }
    int n0 = blockIdx.x * 32, k0 = blockIdx.y * 32;
    int tx = threadIdx.x, ty = threadIdx.y;   // 32 x 8
    #pragma unroll
    for (int i = 0; i < 4; i++) {
        int kr = ty + i * 8;
        t[kr][tx] = src[(size_t)(k0 + kr) * HH + n0 + tx];
    }
    __syncthreads();
    #pragma unroll
    for (int i = 0; i < 4; i++) {
        int nr = ty + i * 8;
        dst[(size_t)(g * HH + n0 + nr) * II + k0 + tx] = __float2half_rn(t[tx][nr]);
    }
}

__global__ void init_kernel() {
    int i = blockIdx.x * blockDim.x + threadIdx.x;
    if (i < 32768) g_hf[0][i] = 0u;
    if (i == 0) { g_cnt = 0u; g_gen = 0u; }
}

// ---------------- phase 1: x_proj = x @ U_all + b  (fp16 mma) ----------------
// C[32768,4096] tiles 128x128, 256 thr (8 warps, 4x2), warp tile 32x64, k-chunk 16.
__global__ __launch_bounds__(256, 2) void xproj_kernel(
    const float* __restrict__ x,
    const float* __restrict__ bf, const float* __restrict__ bi,
    const float* __restrict__ bc, const float* __restrict__ bo)
{
    __shared__ unsigned As[2][128][12];   // 16 halves (8 uints) per row, pad to 12
    __shared__ unsigned Bs[2][128][12];
    const int tid = threadIdx.x, lane = tid & 31, warp = tid >> 5;
    const int wm = warp >> 1, wn = warp & 1;
    const int gq = lane >> 2, tq = lane & 3;
    const int m0 = blockIdx.y * 128, n0 = blockIdx.x * 128;
    const int lrow = tid >> 1, lpart = tid & 1;   // loader mapping: 2 thr/row

    float acc[2][8][4];
    #pragma unroll
    for (int a = 0; a < 2; a++)
        #pragma unroll
        for (int b = 0; b < 8; b++)
            #pragma unroll
            for (int c = 0; c < 4; c++) acc[a][b][c] = 0.f;

    float4 fa0, fa1;
    uint4 ub;
    {   // stage chunk 0
        const float4* xr = (const float4*)(x + (size_t)(m0 + lrow) * II + lpart * 8);
        fa0 = xr[0]; fa1 = xr[1];
        ub = ((const uint4*)(g_Uph + (size_t)(n0 + lrow) * II))[lpart];
    }
    {
        uint4 ua = make_uint4(h2pack(fa0.x, fa0.y), h2pack(fa0.z, fa0.w),
                              h2pack(fa1.x, fa1.y), h2pack(fa1.z, fa1.w));
        *(uint4*)&As[0][lrow][lpart * 4] = ua;
        *(uint4*)&Bs[0][lrow][lpart * 4] = ub;
    }
    __syncthreads();

    const int NK = II / 16;    // 64 chunks
    for (int kc = 0; kc < NK; kc++) {
        int buf = kc & 1;
        if (kc + 1 < NK) {
            const float4* xr = (const float4*)(x + (size_t)(m0 + lrow) * II +
                                               (kc + 1) * 16 + lpart * 8);
            fa0 = xr[0]; fa1 = xr[1];
            ub = ((const uint4*)(g_Uph + (size_t)(n0 + lrow) * II))[(kc + 1) * 2 + lpart];
        }
        {
            unsigned a[2][4], b[8][2];
            #pragma unroll
            for (int mf = 0; mf < 2; mf++) {
                int r = wm * 32 + mf * 16 + gq;
                a[mf][0] = As[buf][r    ][tq];
                a[mf][1] = As[buf][r + 8][tq];
                a[mf][2] = As[buf][r    ][tq + 4];
                a[mf][3] = As[buf][r + 8][tq + 4];
            }
            #pragma unroll
            for (int nf = 0; nf < 8; nf++) {
                int c = wn * 64 + nf * 8 + gq;
                b[nf][0] = Bs[buf][c][tq];
                b[nf][1] = Bs[buf][c][tq + 4];
            }
            #pragma unroll
            for (int mf = 0; mf < 2; mf++)
                #pragma unroll
                for (int nf = 0; nf < 8; nf++)
                    mma16(acc[mf][nf], a[mf], b[nf][0], b[nf][1]);
        }
        if (kc + 1 < NK) {
            int nb = buf ^ 1;
            uint4 ua = make_uint4(h2pack(fa0.x, fa0.y), h2pack(fa0.z, fa0.w),
                                  h2pack(fa1.x, fa1.y), h2pack(fa1.z, fa1.w));
            *(uint4*)&As[nb][lrow][lpart * 4] = ua;
            *(uint4*)&Bs[nb][lrow][lpart * 4] = ub;
        }
        __syncthreads();
    }

    // epilogue: +bias, scatter to (s*64+b) row order
    #pragma unroll
    for (int mf = 0; mf < 2; mf++) {
        int mr = m0 + wm * 32 + mf * 16 + gq;
        int m1 = mr + 8;
        size_t r0 = (size_t)(((mr & 511) << 6) | (mr >> 9)) * NG;
        size_t r1 = (size_t)(((m1 & 511) << 6) | (m1 >> 9)) * NG;
        #pragma unroll
        for (int nf = 0; nf < 8; nf++) {
            int c0 = n0 + wn * 64 + nf * 8 + 2 * tq;
            int gate = c0 >> 10;
            const float* bp = (gate == 0) ? bf : (gate == 1) ? bi : (gate == 2) ? bc : bo;
            float bv0 = bp[c0 & 1023], bv1 = bp[(c0 + 1) & 1023];
            g_xp[r0 + c0    ] = acc[mf][nf][0] + bv0;
            g_xp[r0 + c0 + 1] = acc[mf][nf][1] + bv1;
            g_xp[r1 + c0    ] = acc[mf][nf][2] + bv0;
            g_xp[r1 + c0 + 1] = acc[mf][nf][3] + bv1;
        }
    }
}

// ---------------- persistent recurrence kernel (fp16 mma) ----------------
// 128 CTAs x 512 thr (16 warps = 2 m-slabs x 8 K-splits). CTA j owns hidden cols
// [8j,8j+8) -> 32 gate cols. W fp16 in SMEM (64KB), swizzled; all-4-gate b-frags
// come from 2x LDS.128 per k16. h fp16 in global a-fragment order.
#define SM_W_BYTES   65536
#define SM_RED_BYTES (PTHR * 9 * 16)           // 73728: [(w,lane)][9] float4
#define SM_TOTAL     (SM_W_BYTES + SM_RED_BYTES)

__global__ __launch_bounds__(PTHR, 1) void lstm_persistent(
    float* __restrict__ out, float* __restrict__ out_hs)
{
    extern __shared__ __align__(16) unsigned char sm_raw[];
    float4* red4 = (float4*)(sm_raw + SM_W_BYTES);           // [(w*32+lane)][9] float4

    const int tid = threadIdx.x;
    const int lane = tid & 31, w = tid >> 5;
    const int wm = w & 1, kh = w >> 1;        // 2 m-slabs x 8 K-splits
    const int gq = lane >> 2, tq = lane & 3;
    const int j = blockIdx.x;

    // ---- one-time: load W slice into swizzled fp16 fragment layout ----
    // slot s = gq*4+tq per kk16; 2 uint4 chunks: {g0_lo,g0_hi,g1_lo,g1_hi},{g2..g3}
    // byte addr = kk16*1024 + ((s*32 + chunk*16) ^ (((s>>2)&1)*16))
    const unsigned* Wp_u = (const unsigned*)g_Wph;
    #pragma unroll
    for (int t = 0; t < 8; t++) {
        int job = tid + t * PTHR;            // 4096 jobs = 64 kk16 x 32 slots x 2 chunks
        int kk = job >> 6;
        int rem = job & 63;
        int s  = rem >> 1, chunk = rem & 1;
        int sgq = s >> 2, stq = s & 3;
        int gp = chunk * 2;
        const unsigned* W0 = Wp_u + (size_t)(gp * 1024 + j * 8 + sgq) * 512;
        const unsigned* W1 = W0 + 1024 * 512;
        unsigned lo0 = W0[kk * 8 + stq], hi0 = W0[kk * 8 + stq + 4];
        unsigned lo1 = W1[kk * 8 + stq], hi1 = W1[kk * 8 + stq + 4];
        unsigned swz = ((unsigned)(s >> 2) & 1u) * 16u;
        unsigned off = (unsigned)kk * 1024u + (((unsigned)s * 32u + (unsigned)chunk * 16u) ^ swz);
        *(uint4*)(sm_raw + off) = make_uint4(lo0, hi0, lo1, hi1);
    }
    __syncthreads();

    // ---- per-thread epilogue mapping (one (row, cc) output per thread) ----
    const int rrow = tid >> 3, cc = tid & 7;
    const int r_wm = rrow >> 5, r_mt = (rrow >> 4) & 1;
    const int r_p  = ((rrow >> 3) & 1) * 2 + (cc & 1);
    const int r_lane = (rrow & 7) * 4 + (cc >> 1);
    const int red_f4 = r_lane * 9 + r_mt * 4 + r_p;          // + (kh2*2+r_wm)*32*9
    const int colg = j * 8 + cc;
    // fp16 h write index (half units)
    const int kkj = j >> 1;
    const int hidx = (((kkj * 64 + rrow) * 4 + (cc >> 1)) * 2 + (j & 1)) * 2 + (cc & 1);

    // per-thread b-frag smem offsets (swizzled)
    const int s_me = gq * 4 + tq;
    const unsigned swz_me = ((unsigned)(s_me >> 2) & 1u) * 16u;
    const unsigned woff0 = (((unsigned)s_me * 32u) ^ swz_me);
    const unsigned woff1 = (((unsigned)s_me * 32u + 16u) ^ swz_me);

    float creg = 0.f;
    unsigned gen = 0;

    const int kb16 = kh * 8;                   // this warp's kk16 range (8 slices)
    const int arow = wm * 32 + gq;             // mt0 a-frag row

    // prefetch xp for step 0
    float xr[4];
    #pragma unroll
    for (int g = 0; g < 4; g++)
        xr[g] = __ldg(g_xp + (size_t)rrow * NG + g * 1024 + colg);

    for (int s = 0; s < SS; s++) {
        const uint2* __restrict__ hb = (const uint2*)g_hf[s & 1];
        __half*      __restrict__ hw = (__half*)g_hf[(s + 1) & 1];

        float acc[2][4][4];
        #pragma unroll
        for (int mt = 0; mt < 2; mt++)
            #pragma unroll
            for (int g = 0; g < 4; g++)
                #pragma unroll
                for (int p = 0; p < 4; p++) acc[mt][g][p] = 0.f;

        // 4-deep a-fragment prefetch queue: [slot][row0,row8,row16,row24] uint2
        uint2 qA[4][4];
        #pragma unroll
        for (int p = 0; p < 4; p++) {
            int base = ((kb16 + p) * 64 + arow) * 4 + tq;
            qA[p][0] = __ldcg(hb + base);
            qA[p][1] = __ldcg(hb + base + 32);    // +8 rows
            qA[p][2] = __ldcg(hb + base + 64);    // +16 rows (mt1)
            qA[p][3] = __ldcg(hb + base + 96);
        }

        #pragma unroll
        for (int i = 0; i < 8; i++) {
            int sl = i & 3;
            uint2 u0 = qA[sl][0], u1 = qA[sl][1], u2 = qA[sl][2], u3 = qA[sl][3];
            if (i < 4) {
                int base = ((kb16 + i + 4) * 64 + arow) * 4 + tq;
                qA[sl][0] = __ldcg(hb + base);
                qA[sl][1] = __ldcg(hb + base + 32);
                qA[sl][2] = __ldcg(hb + base + 64);
                qA[sl][3] = __ldcg(hb + base + 96);
            }
            unsigned a0[4] = { u0.x, u1.x, u0.y, u1.y };
            unsigned a1[4] = { u2.x, u3.x, u2.y, u3.y };
            unsigned wb = (unsigned)(kb16 + i) * 1024u;
            uint4 b01 = *(const uint4*)(sm_raw + wb + woff0);
            uint4 b23 = *(const uint4*)(sm_raw + wb + woff1);
            mma16(acc[0][0], a0, b01.x, b01.y);
            mma16(acc[0][1], a0, b01.z, b01.w);
            mma16(acc[0][2], a0, b23.x, b23.y);
            mma16(acc[0][3], a0, b23.z, b23.w);
            mma16(acc[1][0], a1, b01.x, b01.y);
            mma16(acc[1][1], a1, b01.z, b01.w);
            mma16(acc[1][2], a1, b23.x, b23.y);
            mma16(acc[1][3], a1, b23.z, b23.w);
        }

        // dump partials, p-major so epilogue reads are LDS.128
        {
            float4* dst4 = red4 + (w * 32 + lane) * 9;
            #pragma unroll
            for (int mt = 0; mt < 2; mt++)
                #pragma unroll
                for (int p = 0; p < 4; p++)
                    dst4[mt * 4 + p] = make_float4(acc[mt][0][p], acc[mt][1][p],
                                                   acc[mt][2][p], acc[mt][3][p]);
        }
        __syncthreads();

        // unified reduction + gate epilogue: one (row, cc) per thread
        {
            float gs0 = 0.f, gs1 = 0.f, gs2 = 0.f, gs3 = 0.f;
            #pragma unroll
            for (int kh2 = 0; kh2 < 8; kh2++) {
                float4 v = red4[(kh2 * 2 + r_wm) * 32 * 9 + red_f4];
                gs0 += v.x; gs1 += v.y; gs2 += v.z; gs3 += v.w;
            }
            float gf = gs0 + xr[0];
            float gi = gs1 + xr[1];
            float gc = gs2 + xr[2];
            float go = gs3 + xr[3];
            float cn = sigmf(gf) * creg + sigmf(gi) * tanhf(gc);
            creg = cn;
            float hn = sigmf(go) * tanhf(cn);
            st_h_cg(hw + hidx, __float2half_rn(hn));
            out_hs[((size_t)rrow * SS + s) * HH + colg] = hn;
            if (s == SS - 1) {
                out[(size_t)rrow * HH + colg] = hn;
                out[(size_t)BB * HH + (size_t)rrow * HH + colg] = cn;
            }
        }

        // prefetch next step's xp before the barrier (hides L2 latency in the spin)
        if (s + 1 < SS) {
            #pragma unroll
            for (int g = 0; g < 4; g++)
                xr[g] = __ldg(g_xp + (size_t)((s + 1) * 64 + rrow) * NG + g * 1024 + colg);
        }

        // grid barrier (release h_new writes, acquire peers')
        __threadfence();
        __syncthreads();
        gen++;
        if (tid == 0) {
            unsigned t = atomicAdd(&g_cnt, 1u);
            if (t == gen * NCTA - 1u) {
                atomicExch(&g_gen, gen);
            } else {
                unsigned v;
                do {
                    asm volatile("ld.acquire.gpu.global.u32 %0, [%1];"
                                 : "=r"(v) : "l"(&g_gen) : "memory");
                } while (v < gen);
            }
            __threadfence();
        }
        __syncthreads();
    }
}

// ---------------- launch ----------------
extern "C" void kernel_launch(void* const* d_in, const int* in_sizes, int n_in,
                              void* d_out, int out_size)
{
    const float* x  = (const float*)d_in[0];
    const float* Uf = (const float*)d_in[1];
    const float* Ui = (const float*)d_in[2];
    const float* Uc = (const float*)d_in[3];
    const float* Uo = (const float*)d_in[4];
    const float* Wf = (const float*)d_in[5];
    const float* Wi = (const float*)d_in[6];
    const float* Wc = (const float*)d_in[7];
    const float* Wo = (const float*)d_in[8];
    const float* bf = (const float*)d_in[9];
    const float* bi = (const float*)d_in[10];
    const float* bc = (const float*)d_in[11];
    const float* bo = (const float*)d_in[12];
    float* out = (float*)d_out;

    static int smem_set = 0;
    if (!smem_set) {
        cudaFuncSetAttribute(lstm_persistent,
                             cudaFuncAttributeMaxDynamicSharedMemorySize, SM_TOTAL);
        smem_set = 1;
    }

    pack_kernel<<<dim3(32, 32, 8), dim3(32, 8)>>>(Uf, Ui, Uc, Uo, Wf, Wi, Wc, Wo);
    init_kernel<<<(64 * 1024 + 255) / 256, 256>>>();
    xproj_kernel<<<dim3(NG / 128, MMR / 128), 256>>>(x, bf, bi, bc, bo);

    float* hs = out + 2 * BB * HH;   // hidden_seq region
    lstm_persistent<<<NCTA, PTHR, SM_TOTAL>>>(out, hs);
}

// round 10
// speedup vs baseline: 1.5359x; 1.0173x over previous
#include <cuda_runtime.h>
#include <cuda_fp16.h>

#define BB 64
#define SS 512
#define II 1024
#define HH 1024
#define NG 4096          // 4*H
#define MMR (BB*SS)      // 32768
#define NCTA 128
#define PTHR 512

// ---------------- device scratch (no allocs allowed) ----------------
__device__ __align__(16) __half g_Uph[(size_t)NG * II];     // U_all^T [n][k], fp16
__device__ __align__(16) __half g_Wph[(size_t)NG * HH];     // W_all^T [n][k], fp16
__device__ __align__(16) float  g_xp[(size_t)MMR * NG];     // x_proj  [(s*64+b)][4H]
// h fp16 in a-fragment order:
// uint2 index ((kk16*64 + row)*4 + tq); .x = halves(k=16kk16+2tq, +1), .y = halves(+8,+9)
__device__ __align__(16) unsigned g_hf[2][32768];
// two-level grid barrier: 8 group counters (128B-strided) -> root -> broadcast gen
__device__ unsigned g_cnt1[8 * 32];
__device__ unsigned g_cnt2;
__device__ unsigned g_gen;

// ---------------- helpers ----------------
__device__ __forceinline__ unsigned h2pack(float lo, float hi) {
    unsigned u;
    asm("cvt.rn.f16x2.f32 %0, %1, %2;" : "=r"(u) : "f"(hi), "f"(lo));
    return u;
}

__device__ __forceinline__ void mma16(float* d, const unsigned* a, unsigned b0, unsigned b1) {
    asm volatile(
        "mma.sync.aligned.m16n8k16.row.col.f32.f16.f16.f32 "
        "{%0,%1,%2,%3}, {%4,%5,%6,%7}, {%8,%9}, {%0,%1,%2,%3};"
        : "+f"(d[0]), "+f"(d[1]), "+f"(d[2]), "+f"(d[3])
        : "r"(a[0]), "r"(a[1]), "r"(a[2]), "r"(a[3]), "r"(b0), "r"(b1));
}

__device__ __forceinline__ float sigmf(float x) { return 1.f / (1.f + __expf(-x)); }

__device__ __forceinline__ void st_h_cg(__half* p, __half v) {
    unsigned short s = __half_as_ushort(v);
    asm volatile("st.global.cg.u16 [%0], %1;" :: "l"(p), "h"(s) : "memory");
}

__device__ __forceinline__ unsigned ld_acq(const unsigned* p) {
    unsigned v;
    asm volatile("ld.acquire.gpu.global.u32 %0, [%1];" : "=r"(v) : "l"(p) : "memory");
    return v;
}

// ---------------- pack: build K-major fp16 U_all^T / W_all^T ----------------
__global__ void pack_kernel(
    const float* __restrict__ Uf, const float* __restrict__ Ui,
    const float* __restrict__ Uc, const float* __restrict__ Uo,
    const float* __restrict__ Wf, const float* __restrict__ Wi,
    const float* __restrict__ Wc, const float* __restrict__ Wo)
{
    __shared__ float t[32][33];
    int z = blockIdx.z;
    int g = z & 3;
    const float* src;
    __half* dst;
    if (z < 4) { src = (g == 0) ? Uf : (g == 1) ? Ui : (g == 2) ? Uc : Uo; dst = g_Uph; }
    else       { src = (g == 0) ? Wf : (g == 1) ? Wi : (g == 2) ? Wc : Wo; dst = g_Wph; }
    int n0 = blockIdx.x * 32, k0 = blockIdx.y * 32;
    int tx = threadIdx.x, ty = threadIdx.y;   // 32 x 8
    #pragma unroll
    for (int i = 0; i < 4; i++) {
        int kr = ty + i * 8;
        t[kr][tx] = src[(size_t)(k0 + kr) * HH + n0 + tx];
    }
    __syncthreads();
    #pragma unroll
    for (int i = 0; i < 4; i++) {
        int nr = ty + i * 8;
        dst[(size_t)(g * HH + n0 + nr) * II + k0 + tx] = __float2half_rn(t[tx][nr]);
    }
}

__global__ void init_kernel() {
    int i = blockIdx.x * blockDim.x + threadIdx.x;
    if (i < 32768) g_hf[0][i] = 0u;
    if (i < 8 * 32) g_cnt1[i] = 0u;
    if (i == 0) { g_cnt2 = 0u; g_gen = 0u; }
}

// ---------------- phase 1: x_proj = x @ U_all + b  (fp16 mma) ----------------
__global__ __launch_bounds__(256, 2) void xproj_kernel(
    const float* __restrict__ x,
    const float* __restrict__ bf, const float* __restrict__ bi,
    const float* __restrict__ bc, const float* __restrict__ bo)
{
    __shared__ unsigned As[2][128][12];
    __shared__ unsigned Bs[2][128][12];
    const int tid = threadIdx.x, lane = tid & 31, warp = tid >> 5;
    const int wm = warp >> 1, wn = warp & 1;
    const int gq = lane >> 2, tq = lane & 3;
    const int m0 = blockIdx.y * 128, n0 = blockIdx.x * 128;
    const int lrow = tid >> 1, lpart = tid & 1;

    float acc[2][8][4];
    #pragma unroll
    for (int a = 0; a < 2; a++)
        #pragma unroll
        for (int b = 0; b < 8; b++)
            #pragma unroll
            for (int c = 0; c < 4; c++) acc[a][b][c] = 0.f;

    float4 fa0, fa1;
    uint4 ub;
    {
        const float4* xr = (const float4*)(x + (size_t)(m0 + lrow) * II + lpart * 8);
        fa0 = xr[0]; fa1 = xr[1];
        ub = ((const uint4*)(g_Uph + (size_t)(n0 + lrow) * II))[lpart];
    }
    {
        uint4 ua = make_uint4(h2pack(fa0.x, fa0.y), h2pack(fa0.z, fa0.w),
                              h2pack(fa1.x, fa1.y), h2pack(fa1.z, fa1.w));
        *(uint4*)&As[0][lrow][lpart * 4] = ua;
        *(uint4*)&Bs[0][lrow][lpart * 4] = ub;
    }
    __syncthreads();

    const int NK = II / 16;    // 64 chunks
    for (int kc = 0; kc < NK; kc++) {
        int buf = kc & 1;
        if (kc + 1 < NK) {
            const float4* xr = (const float4*)(x + (size_t)(m0 + lrow) * II +
                                               (kc + 1) * 16 + lpart * 8);
            fa0 = xr[0]; fa1 = xr[1];
            ub = ((const uint4*)(g_Uph + (size_t)(n0 + lrow) * II))[(kc + 1) * 2 + lpart];
        }
        {
            unsigned a[2][4], b[8][2];
            #pragma unroll
            for (int mf = 0; mf < 2; mf++) {
                int r = wm * 32 + mf * 16 + gq;
                a[mf][0] = As[buf][r    ][tq];
                a[mf][1] = As[buf][r + 8][tq];
                a[mf][2] = As[buf][r    ][tq + 4];
                a[mf][3] = As[buf][r + 8][tq + 4];
            }
            #pragma unroll
            for (int nf = 0; nf < 8; nf++) {
                int c = wn * 64 + nf * 8 + gq;
                b[nf][0] = Bs[buf][c][tq];
                b[nf][1] = Bs[buf][c][tq + 4];
            }
            #pragma unroll
            for (int mf = 0; mf < 2; mf++)
                #pragma unroll
                for (int nf = 0; nf < 8; nf++)
                    mma16(acc[mf][nf], a[mf], b[nf][0], b[nf][1]);
        }
        if (kc + 1 < NK) {
            int nb = buf ^ 1;
            uint4 ua = make_uint4(h2pack(fa0.x, fa0.y), h2pack(fa0.z, fa0.w),
                                  h2pack(fa1.x, fa1.y), h2pack(fa1.z, fa1.w));
            *(uint4*)&As[nb][lrow][lpart * 4] = ua;
            *(uint4*)&Bs[nb][lrow][lpart * 4] = ub;
        }
        __syncthreads();
    }

    #pragma unroll
    for (int mf = 0; mf < 2; mf++) {
        int mr = m0 + wm * 32 + mf * 16 + gq;
        int m1 = mr + 8;
        size_t r0 = (size_t)(((mr & 511) << 6) | (mr >> 9)) * NG;
        size_t r1 = (size_t)(((m1 & 511) << 6) | (m1 >> 9)) * NG;
        #pragma unroll
        for (int nf = 0; nf < 8; nf++) {
            int c0 = n0 + wn * 64 + nf * 8 + 2 * tq;
            int gate = c0 >> 10;
            const float* bp = (gate == 0) ? bf : (gate == 1) ? bi : (gate == 2) ? bc : bo;
            float bv0 = bp[c0 & 1023], bv1 = bp[(c0 + 1) & 1023];
            g_xp[r0 + c0    ] = acc[mf][nf][0] + bv0;
            g_xp[r0 + c0 + 1] = acc[mf][nf][1] + bv1;
            g_xp[r1 + c0    ] = acc[mf][nf][2] + bv0;
            g_xp[r1 + c0 + 1] = acc[mf][nf][3] + bv1;
        }
    }
}

// ---------------- persistent recurrence kernel (fp16 mma) ----------------
// 128 CTAs x 512 thr (16 warps = 4 m-slabs(16 rows) x 4 K-splits(256)). CTA j owns
// hidden cols [8j,8j+8). W fp16 SMEM (64KB) swizzled; 4-gate b-frags = 2x LDS.128.
// h fp16 in global a-fragment order. Two-level grid barrier.
#define SM_W_BYTES   65536
#define RED_NP       5                          // float4 slots per (warp,lane), 1 pad
#define SM_RED_BYTES (PTHR * RED_NP * 16)       // 40960
#define SM_TOTAL     (SM_W_BYTES + SM_RED_BYTES)

__global__ __launch_bounds__(PTHR, 1) void lstm_persistent(
    float* __restrict__ out, float* __restrict__ out_hs)
{
    extern __shared__ __align__(16) unsigned char sm_raw[];
    float4* red4 = (float4*)(sm_raw + SM_W_BYTES);           // [(w*32+lane)][RED_NP]

    const int tid = threadIdx.x;
    const int lane = tid & 31, w = tid >> 5;
    const int wm = w & 3, kh = w >> 2;        // 4 m-slabs x 4 K-splits
    const int gq = lane >> 2, tq = lane & 3;
    const int j = blockIdx.x;

    // ---- one-time: load W slice into swizzled fp16 fragment layout ----
    const unsigned* Wp_u = (const unsigned*)g_Wph;
    #pragma unroll
    for (int t = 0; t < 8; t++) {
        int job = tid + t * PTHR;            // 4096 jobs = 64 kk16 x 32 slots x 2 chunks
        int kk = job >> 6;
        int rem = job & 63;
        int s  = rem >> 1, chunk = rem & 1;
        int sgq = s >> 2, stq = s & 3;
        int gp = chunk * 2;
        const unsigned* W0 = Wp_u + (size_t)(gp * 1024 + j * 8 + sgq) * 512;
        const unsigned* W1 = W0 + 1024 * 512;
        unsigned lo0 = W0[kk * 8 + stq], hi0 = W0[kk * 8 + stq + 4];
        unsigned lo1 = W1[kk * 8 + stq], hi1 = W1[kk * 8 + stq + 4];
        unsigned swz = ((unsigned)(s >> 2) & 1u) * 16u;
        unsigned off = (unsigned)kk * 1024u + (((unsigned)s * 32u + (unsigned)chunk * 16u) ^ swz);
        *(uint4*)(sm_raw + off) = make_uint4(lo0, hi0, lo1, hi1);
    }
    __syncthreads();

    // ---- per-thread epilogue mapping (one (row, cc) output per thread) ----
    const int rrow = tid >> 3, cc = tid & 7;
    const int r_wm = rrow >> 4;                              // m-slab (16 rows)
    const int r_p  = ((rrow >> 3) & 1) * 2 + (cc & 1);
    const int r_lane = (rrow & 7) * 4 + (cc >> 1);
    const int colg = j * 8 + cc;
    const int kkj = j >> 1;
    const int hidx = (((kkj * 64 + rrow) * 4 + (cc >> 1)) * 2 + (j & 1)) * 2 + (cc & 1);

    // per-thread b-frag smem offsets (swizzled)
    const int s_me = gq * 4 + tq;
    const unsigned swz_me = ((unsigned)(s_me >> 2) & 1u) * 16u;
    const unsigned woff0 = (((unsigned)s_me * 32u) ^ swz_me);
    const unsigned woff1 = (((unsigned)s_me * 32u + 16u) ^ swz_me);

    const int grp = j >> 4;                    // barrier group (8 groups of 16)

    float creg = 0.f;
    unsigned gen = 0;

    const int kb16 = kh * 16;                  // this warp's kk16 range (16 slices)
    const int arow = wm * 16 + gq;             // a-frag row

    // prefetch xp for step 0
    float xr[4];
    #pragma unroll
    for (int g = 0; g < 4; g++)
        xr[g] = __ldg(g_xp + (size_t)rrow * NG + g * 1024 + colg);

    for (int s = 0; s < SS; s++) {
        const uint2* __restrict__ hb = (const uint2*)g_hf[s & 1];
        __half*      __restrict__ hw = (__half*)g_hf[(s + 1) & 1];

        float acc[4][4];
        #pragma unroll
        for (int g = 0; g < 4; g++)
            #pragma unroll
            for (int p = 0; p < 4; p++) acc[g][p] = 0.f;

        // 4-deep a-fragment prefetch queue: [slot][row, row+8] uint2
        uint2 qA[4][2];
        #pragma unroll
        for (int p = 0; p < 4; p++) {
            int base = ((kb16 + p) * 64 + arow) * 4 + tq;
            qA[p][0] = __ldcg(hb + base);
            qA[p][1] = __ldcg(hb + base + 32);    // +8 rows
        }

        #pragma unroll 4
        for (int i = 0; i < 16; i++) {
            int sl = i & 3;
            uint2 u0 = qA[sl][0], u1 = qA[sl][1];
            if (i < 12) {
                int base = ((kb16 + i + 4) * 64 + arow) * 4 + tq;
                qA[sl][0] = __ldcg(hb + base);
                qA[sl][1] = __ldcg(hb + base + 32);
            }
            unsigned a0[4] = { u0.x, u1.x, u0.y, u1.y };
            unsigned wb = (unsigned)(kb16 + i) * 1024u;
            uint4 b01 = *(const uint4*)(sm_raw + wb + woff0);
            uint4 b23 = *(const uint4*)(sm_raw + wb + woff1);
            mma16(acc[0], a0, b01.x, b01.y);
            mma16(acc[1], a0, b01.z, b01.w);
            mma16(acc[2], a0, b23.x, b23.y);
            mma16(acc[3], a0, b23.z, b23.w);
        }

        // dump partials, p-major float4, padded stride (conflict-free STS.128)
        {
            float4* dst4 = red4 + (w * 32 + lane) * RED_NP;
            #pragma unroll
            for (int p = 0; p < 4; p++)
                dst4[p] = make_float4(acc[0][p], acc[1][p], acc[2][p], acc[3][p]);
        }
        __syncthreads();

        // unified reduction (4 partials) + gate epilogue: one (row, cc) per thread
        float hn, cn;
        {
            float gs0 = 0.f, gs1 = 0.f, gs2 = 0.f, gs3 = 0.f;
            #pragma unroll
            for (int kh2 = 0; kh2 < 4; kh2++) {
                float4 v = red4[((kh2 * 4 + r_wm) * 32 + r_lane) * RED_NP + r_p];
                gs0 += v.x; gs1 += v.y; gs2 += v.z; gs3 += v.w;
            }
            float gf = gs0 + xr[0];
            float gi = gs1 + xr[1];
            float gc = gs2 + xr[2];
            float go = gs3 + xr[3];
            cn = sigmf(gf) * creg + sigmf(gi) * tanhf(gc);
            creg = cn;
            hn = sigmf(go) * tanhf(cn);
            st_h_cg(hw + hidx, __float2half_rn(hn));
        }

        // release h_new, arrive on two-level barrier
        __threadfence();
        __syncthreads();
        gen++;
        if (tid == 0) {
            unsigned t = atomicAdd(&g_cnt1[grp * 32], 1u);
            if (t == gen * 16u - 1u) {
                unsigned r = atomicAdd(&g_cnt2, 1u);
                if (r == gen * 8u - 1u)
                    atomicExch(&g_gen, gen);
            }
        }

        // overlap with barrier wait: hidden_seq store + next xp prefetch
        out_hs[((size_t)rrow * SS + s) * HH + colg] = hn;
        if (s == SS - 1) {
            out[(size_t)rrow * HH + colg] = hn;
            out[(size_t)BB * HH + (size_t)rrow * HH + colg] = cn;
        } else {
            #pragma unroll
            for (int g = 0; g < 4; g++)
                xr[g] = __ldg(g_xp + (size_t)((s + 1) * 64 + rrow) * NG + g * 1024 + colg);
        }

        if (tid == 0) {
            while (ld_acq(&g_gen) < gen) { }
        }
        __syncthreads();
    }
}

// ---------------- launch ----------------
extern "C" void kernel_launch(void* const* d_in, const int* in_sizes, int n_in,
                              void* d_out, int out_size)
{
    const float* x  = (const float*)d_in[0];
    const float* Uf = (const float*)d_in[1];
    const float* Ui = (const float*)d_in[2];
    const float* Uc = (const float*)d_in[3];
    const float* Uo = (const float*)d_in[4];
    const float* Wf = (const float*)d_in[5];
    const float* Wi = (const float*)d_in[6];
    const float* Wc = (const float*)d_in[7];
    const float* Wo = (const float*)d_in[8];
    const float* bf = (const float*)d_in[9];
    const float* bi = (const float*)d_in[10];
    const float* bc = (const float*)d_in[11];
    const float* bo = (const float*)d_in[12];
    float* out = (float*)d_out;

    static int smem_set = 0;
    if (!smem_set) {
        cudaFuncSetAttribute(lstm_persistent,
                             cudaFuncAttributeMaxDynamicSharedMemorySize, SM_TOTAL);
        smem_set = 1;
    }

    pack_kernel<<<dim3(32, 32, 8), dim3(32, 8)>>>(Uf, Ui, Uc, Uo, Wf, Wi, Wc, Wo);
    init_kernel<<<(32768 + 255) / 256, 256>>>();
    xproj_kernel<<<dim3(NG / 128, MMR / 128), 256>>>(x, bf, bi, bc, bo);

    float* hs = out + 2 * BB * HH;   // hidden_seq region
    lstm_persistent<<<NCTA, PTHR, SM_TOTAL>>>(out, hs);
}

// round 11
// speedup vs baseline: 1.5735x; 1.0245x over previous
#include <cuda_runtime.h>
#include <cuda_fp16.h>

#define BB 64
#define SS 512
#define II 1024
#define HH 1024
#define NG 4096          // 4*H
#define MMR (BB*SS)      // 32768
#define NCTA 128
#define PTHR 512

// ---------------- device scratch (no allocs allowed) ----------------
__device__ __align__(16) __half g_Uph[(size_t)NG * II];     // U_all^T [n][k], fp16
__device__ __align__(16) __half g_Wph[(size_t)NG * HH];     // W_all^T [n][k], fp16
__device__ __align__(16) __half g_xh[(size_t)MMR * II];     // x in fp16 (row-major, k contig)
__device__ __align__(16) float  g_xp[(size_t)MMR * NG];     // x_proj  [(s*64+b)][4H]
// h fp16 in a-fragment order:
// uint2 index ((kk16*64 + row)*4 + tq); .x = halves(k=16kk16+2tq, +1), .y = halves(+8,+9)
__device__ __align__(16) unsigned g_hf[2][32768];
// two-level grid barrier: 8 group counters (128B-strided) -> root -> broadcast gen
__device__ unsigned g_cnt1[8 * 32];
__device__ unsigned g_cnt2;
__device__ unsigned g_gen;

// ---------------- helpers ----------------
__device__ __forceinline__ unsigned h2pack(float lo, float hi) {
    unsigned u;
    asm("cvt.rn.f16x2.f32 %0, %1, %2;" : "=r"(u) : "f"(hi), "f"(lo));
    return u;
}

__device__ __forceinline__ void mma16(float* d, const unsigned* a, unsigned b0, unsigned b1) {
    asm volatile(
        "mma.sync.aligned.m16n8k16.row.col.f32.f16.f16.f32 "
        "{%0,%1,%2,%3}, {%4,%5,%6,%7}, {%8,%9}, {%0,%1,%2,%3};"
        : "+f"(d[0]), "+f"(d[1]), "+f"(d[2]), "+f"(d[3])
        : "r"(a[0]), "r"(a[1]), "r"(a[2]), "r"(a[3]), "r"(b0), "r"(b1));
}

__device__ __forceinline__ float sigmf(float x) { return 1.f / (1.f + __expf(-x)); }

__device__ __forceinline__ void st_h_cg(__half* p, __half v) {
    unsigned short s = __half_as_ushort(v);
    asm volatile("st.global.cg.u16 [%0], %1;" :: "l"(p), "h"(s) : "memory");
}

__device__ __forceinline__ unsigned ld_acq(const unsigned* p) {
    unsigned v;
    asm volatile("ld.acquire.gpu.global.u32 %0, [%1];" : "=r"(v) : "l"(p) : "memory");
    return v;
}

// ---------------- pack: build K-major fp16 U_all^T / W_all^T ----------------
__global__ void pack_kernel(
    const float* __restrict__ Uf, const float* __restrict__ Ui,
    const float* __restrict__ Uc, const float* __restrict__ Uo,
    const float* __restrict__ Wf, const float* __restrict__ Wi,
    const float* __restrict__ Wc, const float* __restrict__ Wo)
{
    __shared__ float t[32][33];
    int z = blockIdx.z;
    int g = z & 3;
    const float* src;
    __half* dst;
    if (z < 4) { src = (g == 0) ? Uf : (g == 1) ? Ui : (g == 2) ? Uc : Uo; dst = g_Uph; }
    else       { src = (g == 0) ? Wf : (g == 1) ? Wi : (g == 2) ? Wc : Wo; dst = g_Wph; }
    int n0 = blockIdx.x * 32, k0 = blockIdx.y * 32;
    int tx = threadIdx.x, ty = threadIdx.y;   // 32 x 8
    #pragma unroll
    for (int i = 0; i < 4; i++) {
        int kr = ty + i * 8;
        t[kr][tx] = src[(size_t)(k0 + kr) * HH + n0 + tx];
    }
    __syncthreads();
    #pragma unroll
    for (int i = 0; i < 4; i++) {
        int nr = ty + i * 8;
        dst[(size_t)(g * HH + n0 + nr) * II + k0 + tx] = __float2half_rn(t[tx][nr]);
    }
}

// ---------------- x fp32 -> fp16 ----------------
__global__ void xconv_kernel(const float* __restrict__ x) {
    size_t i = ((size_t)blockIdx.x * 256 + threadIdx.x) * 8;
    float4 a = *(const float4*)(x + i);
    float4 b = *(const float4*)(x + i + 4);
    uint4 u = make_uint4(h2pack(a.x, a.y), h2pack(a.z, a.w),
                         h2pack(b.x, b.y), h2pack(b.z, b.w));
    *(uint4*)((__half*)g_xh + i) = u;
}

__global__ void init_kernel() {
    int i = blockIdx.x * blockDim.x + threadIdx.x;
    if (i < 32768) g_hf[0][i] = 0u;
    if (i < 8 * 32) g_cnt1[i] = 0u;
    if (i == 0) { g_cnt2 = 0u; g_gen = 0u; }
}

// ---------------- phase 1: x_proj = x @ U_all + b  (fp16 mma, 128x256 tile) ----------------
// 512 thr = 16 warps (4m x 4n), warp tile 32x64, k-chunk 16, double-buffered.
__global__ __launch_bounds__(512, 1) void xproj_kernel(
    const float* __restrict__ bf, const float* __restrict__ bi,
    const float* __restrict__ bc, const float* __restrict__ bo)
{
    __shared__ unsigned As[2][128][12];
    __shared__ unsigned Bs[2][256][12];
    const int tid = threadIdx.x, lane = tid & 31, warp = tid >> 5;
    const int wm = warp >> 2, wn = warp & 3;
    const int gq = lane >> 2, tq = lane & 3;
    const int m0 = blockIdx.y * 128, n0 = blockIdx.x * 256;
    const int arow = tid >> 1, apart = tid & 1;   // A loader (tid<256): 2 thr/row
    const int brow = tid >> 1, bpart = tid & 1;   // B loader (all): 2 thr/row

    float acc[2][8][4];
    #pragma unroll
    for (int a = 0; a < 2; a++)
        #pragma unroll
        for (int b = 0; b < 8; b++)
            #pragma unroll
            for (int c = 0; c < 4; c++) acc[a][b][c] = 0.f;

    uint4 ra, rb;
    {   // stage chunk 0
        if (tid < 256)
            ra = *(const uint4*)(g_xh + (size_t)(m0 + arow) * II + apart * 8);
        rb = *(const uint4*)(g_Uph + (size_t)(n0 + brow) * II + bpart * 8);
    }
    {
        if (tid < 256) *(uint4*)&As[0][arow][apart * 4] = ra;
        *(uint4*)&Bs[0][brow][bpart * 4] = rb;
    }
    __syncthreads();

    const int NK = II / 16;    // 64 chunks
    for (int kc = 0; kc < NK; kc++) {
        int buf = kc & 1;
        if (kc + 1 < NK) {
            int kb = (kc + 1) * 16;
            if (tid < 256)
                ra = *(const uint4*)(g_xh + (size_t)(m0 + arow) * II + kb + apart * 8);
            rb = *(const uint4*)(g_Uph + (size_t)(n0 + brow) * II + kb + bpart * 8);
        }
        {
            unsigned a[2][4], b[8][2];
            #pragma unroll
            for (int mf = 0; mf < 2; mf++) {
                int r = wm * 32 + mf * 16 + gq;
                a[mf][0] = As[buf][r    ][tq];
                a[mf][1] = As[buf][r + 8][tq];
                a[mf][2] = As[buf][r    ][tq + 4];
                a[mf][3] = As[buf][r + 8][tq + 4];
            }
            #pragma unroll
            for (int nf = 0; nf < 8; nf++) {
                int c = wn * 64 + nf * 8 + gq;
                b[nf][0] = Bs[buf][c][tq];
                b[nf][1] = Bs[buf][c][tq + 4];
            }
            #pragma unroll
            for (int mf = 0; mf < 2; mf++)
                #pragma unroll
                for (int nf = 0; nf < 8; nf++)
                    mma16(acc[mf][nf], a[mf], b[nf][0], b[nf][1]);
        }
        if (kc + 1 < NK) {
            int nb = buf ^ 1;
            if (tid < 256) *(uint4*)&As[nb][arow][apart * 4] = ra;
            *(uint4*)&Bs[nb][brow][bpart * 4] = rb;
        }
        __syncthreads();
    }

    // epilogue: +bias, scatter to (s*64+b) row order
    #pragma unroll
    for (int mf = 0; mf < 2; mf++) {
        int mr = m0 + wm * 32 + mf * 16 + gq;
        int m1 = mr + 8;
        size_t r0 = (size_t)(((mr & 511) << 6) | (mr >> 9)) * NG;
        size_t r1 = (size_t)(((m1 & 511) << 6) | (m1 >> 9)) * NG;
        #pragma unroll
        for (int nf = 0; nf < 8; nf++) {
            int c0 = n0 + wn * 64 + nf * 8 + 2 * tq;
            int gate = c0 >> 10;
            const float* bp = (gate == 0) ? bf : (gate == 1) ? bi : (gate == 2) ? bc : bo;
            float bv0 = bp[c0 & 1023], bv1 = bp[(c0 + 1) & 1023];
            g_xp[r0 + c0    ] = acc[mf][nf][0] + bv0;
            g_xp[r0 + c0 + 1] = acc[mf][nf][1] + bv1;
            g_xp[r1 + c0    ] = acc[mf][nf][2] + bv0;
            g_xp[r1 + c0 + 1] = acc[mf][nf][3] + bv1;
        }
    }
}

// ---------------- persistent recurrence kernel (fp16 mma) ----------------
// 128 CTAs x 512 thr (16 warps = 4 m-slabs(16 rows) x 4 K-splits(256)). CTA j owns
// hidden cols [8j,8j+8). W fp16 SMEM (64KB) swizzled; 4-gate b-frags = 2x LDS.128.
// h fp16 in global a-fragment order. Two-level grid barrier.
#define SM_W_BYTES   65536
#define RED_NP       5                          // float4 slots per (warp,lane), 1 pad
#define SM_RED_BYTES (PTHR * RED_NP * 16)       // 40960
#define SM_TOTAL     (SM_W_BYTES + SM_RED_BYTES)

__global__ __launch_bounds__(PTHR, 1) void lstm_persistent(
    float* __restrict__ out, float* __restrict__ out_hs)
{
    extern __shared__ __align__(16) unsigned char sm_raw[];
    float4* red4 = (float4*)(sm_raw + SM_W_BYTES);           // [(w*32+lane)][RED_NP]

    const int tid = threadIdx.x;
    const int lane = tid & 31, w = tid >> 5;
    const int wm = w & 3, kh = w >> 2;        // 4 m-slabs x 4 K-splits
    const int gq = lane >> 2, tq = lane & 3;
    const int j = blockIdx.x;

    // ---- one-time: load W slice into swizzled fp16 fragment layout ----
    const unsigned* Wp_u = (const unsigned*)g_Wph;
    #pragma unroll
    for (int t = 0; t < 8; t++) {
        int job = tid + t * PTHR;            // 4096 jobs = 64 kk16 x 32 slots x 2 chunks
        int kk = job >> 6;
        int rem = job & 63;
        int s  = rem >> 1, chunk = rem & 1;
        int sgq = s >> 2, stq = s & 3;
        int gp = chunk * 2;
        const unsigned* W0 = Wp_u + (size_t)(gp * 1024 + j * 8 + sgq) * 512;
        const unsigned* W1 = W0 + 1024 * 512;
        unsigned lo0 = W0[kk * 8 + stq], hi0 = W0[kk * 8 + stq + 4];
        unsigned lo1 = W1[kk * 8 + stq], hi1 = W1[kk * 8 + stq + 4];
        unsigned swz = ((unsigned)(s >> 2) & 1u) * 16u;
        unsigned off = (unsigned)kk * 1024u + (((unsigned)s * 32u + (unsigned)chunk * 16u) ^ swz);
        *(uint4*)(sm_raw + off) = make_uint4(lo0, hi0, lo1, hi1);
    }
    __syncthreads();

    // ---- per-thread epilogue mapping (one (row, cc) output per thread) ----
    const int rrow = tid >> 3, cc = tid & 7;
    const int r_wm = rrow >> 4;                              // m-slab (16 rows)
    const int r_p  = ((rrow >> 3) & 1) * 2 + (cc & 1);
    const int r_lane = (rrow & 7) * 4 + (cc >> 1);
    const int colg = j * 8 + cc;
    const int kkj = j >> 1;
    const int hidx = (((kkj * 64 + rrow) * 4 + (cc >> 1)) * 2 + (j & 1)) * 2 + (cc & 1);

    // per-thread b-frag smem offsets (swizzled)
    const int s_me = gq * 4 + tq;
    const unsigned swz_me = ((unsigned)(s_me >> 2) & 1u) * 16u;
    const unsigned woff0 = (((unsigned)s_me * 32u) ^ swz_me);
    const unsigned woff1 = (((unsigned)s_me * 32u + 16u) ^ swz_me);

    const int grp = j >> 4;                    // barrier group (8 groups of 16)

    float creg = 0.f;
    unsigned gen = 0;

    const int kb16 = kh * 16;                  // this warp's kk16 range (16 slices)
    const int arow = wm * 16 + gq;             // a-frag row

    // prefetch xp for step 0
    float xr[4];
    #pragma unroll
    for (int g = 0; g < 4; g++)
        xr[g] = __ldg(g_xp + (size_t)rrow * NG + g * 1024 + colg);

    for (int s = 0; s < SS; s++) {
        const uint2* __restrict__ hb = (const uint2*)g_hf[s & 1];
        __half*      __restrict__ hw = (__half*)g_hf[(s + 1) & 1];

        float acc[4][4];
        #pragma unroll
        for (int g = 0; g < 4; g++)
            #pragma unroll
            for (int p = 0; p < 4; p++) acc[g][p] = 0.f;

        // 4-deep a-fragment prefetch queue: [slot][row, row+8] uint2
        uint2 qA[4][2];
        #pragma unroll
        for (int p = 0; p < 4; p++) {
            int base = ((kb16 + p) * 64 + arow) * 4 + tq;
            qA[p][0] = __ldcg(hb + base);
            qA[p][1] = __ldcg(hb + base + 32);    // +8 rows
        }

        #pragma unroll 4
        for (int i = 0; i < 16; i++) {
            int sl = i & 3;
            uint2 u0 = qA[sl][0], u1 = qA[sl][1];
            if (i < 12) {
                int base = ((kb16 + i + 4) * 64 + arow) * 4 + tq;
                qA[sl][0] = __ldcg(hb + base);
                qA[sl][1] = __ldcg(hb + base + 32);
            }
            unsigned a0[4] = { u0.x, u1.x, u0.y, u1.y };
            unsigned wb = (unsigned)(kb16 + i) * 1024u;
            uint4 b01 = *(const uint4*)(sm_raw + wb + woff0);
            uint4 b23 = *(const uint4*)(sm_raw + wb + woff1);
            mma16(acc[0], a0, b01.x, b01.y);
            mma16(acc[1], a0, b01.z, b01.w);
            mma16(acc[2], a0, b23.x, b23.y);
            mma16(acc[3], a0, b23.z, b23.w);
        }

        // dump partials, p-major float4, padded stride (conflict-free STS.128)
        {
            float4* dst4 = red4 + (w * 32 + lane) * RED_NP;
            #pragma unroll
            for (int p = 0; p < 4; p++)
                dst4[p] = make_float4(acc[0][p], acc[1][p], acc[2][p], acc[3][p]);
        }
        __syncthreads();

        // unified reduction (4 partials) + gate epilogue: one (row, cc) per thread
        float hn, cn;
        {
            float gs0 = 0.f, gs1 = 0.f, gs2 = 0.f, gs3 = 0.f;
            #pragma unroll
            for (int kh2 = 0; kh2 < 4; kh2++) {
                float4 v = red4[((kh2 * 4 + r_wm) * 32 + r_lane) * RED_NP + r_p];
                gs0 += v.x; gs1 += v.y; gs2 += v.z; gs3 += v.w;
            }
            float gf = gs0 + xr[0];
            float gi = gs1 + xr[1];
            float gc = gs2 + xr[2];
            float go = gs3 + xr[3];
            cn = sigmf(gf) * creg + sigmf(gi) * tanhf(gc);
            creg = cn;
            hn = sigmf(go) * tanhf(cn);
            st_h_cg(hw + hidx, __float2half_rn(hn));
        }

        // release h_new, arrive on two-level barrier
        __threadfence();
        __syncthreads();
        gen++;
        if (tid == 0) {
            unsigned t = atomicAdd(&g_cnt1[grp * 32], 1u);
            if (t == gen * 16u - 1u) {
                unsigned r = atomicAdd(&g_cnt2, 1u);
                if (r == gen * 8u - 1u)
                    atomicExch(&g_gen, gen);
            }
        }

        // overlap with barrier wait: hidden_seq store + next xp prefetch
        out_hs[((size_t)rrow * SS + s) * HH + colg] = hn;
        if (s == SS - 1) {
            out[(size_t)rrow * HH + colg] = hn;
            out[(size_t)BB * HH + (size_t)rrow * HH + colg] = cn;
        } else {
            #pragma unroll
            for (int g = 0; g < 4; g++)
                xr[g] = __ldg(g_xp + (size_t)((s + 1) * 64 + rrow) * NG + g * 1024 + colg);
        }

        if (tid == 0) {
            while (ld_acq(&g_gen) < gen) { }
        }
        __syncthreads();
    }
}

// ---------------- launch ----------------
extern "C" void kernel_launch(void* const* d_in, const int* in_sizes, int n_in,
                              void* d_out, int out_size)
{
    const float* x  = (const float*)d_in[0];
    const float* Uf = (const float*)d_in[1];
    const float* Ui = (const float*)d_in[2];
    const float* Uc = (const float*)d_in[3];
    const float* Uo = (const float*)d_in[4];
    const float* Wf = (const float*)d_in[5];
    const float* Wi = (const float*)d_in[6];
    const float* Wc = (const float*)d_in[7];
    const float* Wo = (const float*)d_in[8];
    const float* bf = (const float*)d_in[9];
    const float* bi = (const float*)d_in[10];
    const float* bc = (const float*)d_in[11];
    const float* bo = (const float*)d_in[12];
    float* out = (float*)d_out;

    static int smem_set = 0;
    if (!smem_set) {
        cudaFuncSetAttribute(lstm_persistent,
                             cudaFuncAttributeMaxDynamicSharedMemorySize, SM_TOTAL);
        smem_set = 1;
    }

    pack_kernel<<<dim3(32, 32, 8), dim3(32, 8)>>>(Uf, Ui, Uc, Uo, Wf, Wi, Wc, Wo);
    xconv_kernel<<<(MMR * II) / (256 * 8), 256>>>(x);
    init_kernel<<<(32768 + 255) / 256, 256>>>();
    xproj_kernel<<<dim3(NG / 256, MMR / 128), 512>>>(bf, bi, bc, bo);

    float* hs = out + 2 * BB * HH;   // hidden_seq region
    lstm_persistent<<<NCTA, PTHR, SM_TOTAL>>>(out, hs);
}

// round 13
// speedup vs baseline: 1.7354x; 1.1029x over previous
#include <cuda_runtime.h>
#include <cuda_fp16.h>

#define BB 64
#define SS 512
#define II 1024
#define HH 1024
#define NG 4096          // 4*H
#define MMR (BB*SS)      // 32768
#define NCTA 128
#define PTHR 512

// ---------------- device scratch (no allocs allowed) ----------------
__device__ __align__(16) __half g_Uph[(size_t)NG * II];     // U_all^T [n][k], fp16
__device__ __align__(16) __half g_Wph[(size_t)NG * HH];     // W_all^T [n][k], fp16
// x fp16 in a-fragment order per step: uint2 g_xf[s][ (kk16*64 + row)*4 + tq ]
//   .x = halves(k=16kk16+2tq, +1), .y = halves(+8, +9); row = batch b
__device__ __align__(16) uint2 g_xf[(size_t)SS * 16384];
// h fp16 in a-fragment order (same convention), double buffered
__device__ __align__(16) unsigned g_hf[2][32768];
// two-level grid barrier: 8 group counters (128B-strided) -> root -> broadcast gen
__device__ unsigned g_cnt1[8 * 32];
__device__ unsigned g_cnt2;
__device__ unsigned g_gen;

// ---------------- helpers ----------------
__device__ __forceinline__ unsigned h2pack(float lo, float hi) {
    unsigned u;
    asm("cvt.rn.f16x2.f32 %0, %1, %2;" : "=r"(u) : "f"(hi), "f"(lo));
    return u;
}

__device__ __forceinline__ void mma16(float* d, const unsigned* a, unsigned b0, unsigned b1) {
    asm volatile(
        "mma.sync.aligned.m16n8k16.row.col.f32.f16.f16.f32 "
        "{%0,%1,%2,%3}, {%4,%5,%6,%7}, {%8,%9}, {%0,%1,%2,%3};"
        : "+f"(d[0]), "+f"(d[1]), "+f"(d[2]), "+f"(d[3])
        : "r"(a[0]), "r"(a[1]), "r"(a[2]), "r"(a[3]), "r"(b0), "r"(b1));
}

__device__ __forceinline__ float sigmf(float x) { return 1.f / (1.f + __expf(-x)); }

__device__ __forceinline__ void st_h_cg(__half* p, __half v) {
    unsigned short s = __half_as_ushort(v);
    asm volatile("st.global.cg.u16 [%0], %1;" :: "l"(p), "h"(s) : "memory");
}

__device__ __forceinline__ unsigned ld_acq(const unsigned* p) {
    unsigned v;
    asm volatile("ld.acquire.gpu.global.u32 %0, [%1];" : "=r"(v) : "l"(p) : "memory");
    return v;
}

// ---------------- pack: build K-major fp16 U_all^T / W_all^T ----------------
__global__ void pack_kernel(
    const float* __restrict__ Uf, const float* __restrict__ Ui,
    const float* __restrict__ Uc, const float* __restrict__ Uo,
    const float* __restrict__ Wf, const float* __restrict__ Wi,
    const float* __restrict__ Wc, const float* __restrict__ Wo)
{
    __shared__ float t[32][33];
    int z = blockIdx.z;
    int g = z & 3;
    const float* src;
    __half* dst;
    if (z < 4) { src = (g == 0) ? Uf : (g == 1) ? Ui : (g == 2) ? Uc : Uo; dst = g_Uph; }
    else       { src = (g == 0) ? Wf : (g == 1) ? Wi : (g == 2) ? Wc : Wo; dst = g_Wph; }
    int n0 = blockIdx.x * 32, k0 = blockIdx.y * 32;
    int tx = threadIdx.x, ty = threadIdx.y;   // 32 x 8
    #pragma unroll
    for (int i = 0; i < 4; i++) {
        int kr = ty + i * 8;
        t[kr][tx] = src[(size_t)(k0 + kr) * HH + n0 + tx];
    }
    __syncthreads();
    #pragma unroll
    for (int i = 0; i < 4; i++) {
        int nr = ty + i * 8;
        dst[(size_t)(g * HH + n0 + nr) * II + k0 + tx] = __float2half_rn(t[tx][nr]);
    }
}

// ---------------- x fp32 -> fp16 a-fragment order ----------------
// Job space: SS*16384 = 2^23 jobs, one uint2 each.
// idx bits: tq(2) | row(6) | kk(6) | s(9)
__global__ void xconv_kernel(const float* __restrict__ x) {
    int idx = blockIdx.x * 256 + threadIdx.x;
    if (idx >= SS * 16384) return;
    int tq  = idx & 3;
    int row = (idx >> 2) & 63;
    int kk  = (idx >> 8) & 63;
    int s   = idx >> 14;
    const float* xr = x + ((size_t)row * SS + s) * II + kk * 16;
    float2 lo = *(const float2*)(xr + 2 * tq);
    float2 hi = *(const float2*)(xr + 2 * tq + 8);
    g_xf[(size_t)s * 16384 + (kk * 64 + row) * 4 + tq] =
        make_uint2(h2pack(lo.x, lo.y), h2pack(hi.x, hi.y));
}

__global__ void init_kernel() {
    int i = blockIdx.x * blockDim.x + threadIdx.x;
    if (i < 32768) g_hf[0][i] = 0u;
    if (i < 8 * 32) g_cnt1[i] = 0u;
    if (i == 0) { g_cnt2 = 0u; g_gen = 0u; }
}

// ---------------- fused persistent kernel ----------------
// 128 CTAs x 512 thr (16 warps = 4 m-slabs(16 rows) x 4 K-splits(256)). CTA j owns
// hidden cols [8j,8j+8). W and U fp16 SMEM (64KB each), swizzled; 4-gate b-frags =
// 2x LDS.128. h and x fp16 in global a-fragment order. Each step: h-GEMM -> gate
// epilogue -> publish h -> ARRIVE -> xp-GEMM for s+1 in barrier slack -> spin.
#define SM_W_BYTES   65536
#define SM_U_BASE    65536
#define RED_BASE     131072
#define RED_NP       5                          // float4 slots per (warp,lane), 1 pad
#define SM_RED_BYTES (PTHR * RED_NP * 16)       // 40960
#define SM_TOTAL     (RED_BASE + SM_RED_BYTES)  // 172032

__global__ __launch_bounds__(PTHR, 1) void lstm_persistent(
    float* __restrict__ out, float* __restrict__ out_hs,
    const float* __restrict__ bf, const float* __restrict__ bi,
    const float* __restrict__ bc, const float* __restrict__ bo)
{
    extern __shared__ __align__(16) unsigned char sm_raw[];
    float4* red4 = (float4*)(sm_raw + RED_BASE);             // [(w*32+lane)][RED_NP]

    const int tid = threadIdx.x;
    const int lane = tid & 31, w = tid >> 5;
    const int wm = w & 3, kh = w >> 2;        // 4 m-slabs x 4 K-splits
    const int gq = lane >> 2, tq = lane & 3;
    const int j = blockIdx.x;

    // ---- one-time: pack W and U slices into swizzled fp16 fragment layout ----
    #pragma unroll
    for (int src = 0; src < 2; src++) {
        const unsigned* Wp_u = (const unsigned*)(src == 0 ? g_Wph : g_Uph);
        unsigned obase = src == 0 ? 0u : (unsigned)SM_U_BASE;
        #pragma unroll
        for (int t = 0; t < 8; t++) {
            int job = tid + t * PTHR;        // 4096 jobs = 64 kk16 x 32 slots x 2 chunks
            int kk = job >> 6;
            int rem = job & 63;
            int s  = rem >> 1, chunk = rem & 1;
            int sgq = s >> 2, stq = s & 3;
            int gp = chunk * 2;
            const unsigned* W0 = Wp_u + (size_t)(gp * 1024 + j * 8 + sgq) * 512;
            const unsigned* W1 = W0 + 1024 * 512;
            unsigned lo0 = W0[kk * 8 + stq], hi0 = W0[kk * 8 + stq + 4];
            unsigned lo1 = W1[kk * 8 + stq], hi1 = W1[kk * 8 + stq + 4];
            unsigned swz = ((unsigned)(s >> 2) & 1u) * 16u;
            unsigned off = obase + (unsigned)kk * 1024u +
                           (((unsigned)s * 32u + (unsigned)chunk * 16u) ^ swz);
            *(uint4*)(sm_raw + off) = make_uint4(lo0, hi0, lo1, hi1);
        }
    }
    __syncthreads();

    // ---- per-thread epilogue mapping (one (row, cc) output per thread) ----
    const int rrow = tid >> 3, cc = tid & 7;
    const int r_wm = rrow >> 4;                              // m-slab (16 rows)
    const int r_p  = ((rrow >> 3) & 1) * 2 + (cc & 1);
    const int r_lane = (rrow & 7) * 4 + (cc >> 1);
    const int colg = j * 8 + cc;
    const int kkj = j >> 1;
    const int hidx = (((kkj * 64 + rrow) * 4 + (cc >> 1)) * 2 + (j & 1)) * 2 + (cc & 1);

    // per-thread b-frag smem offsets (swizzled)
    const int s_me = gq * 4 + tq;
    const unsigned swz_me = ((unsigned)(s_me >> 2) & 1u) * 16u;
    const unsigned woff0 = (((unsigned)s_me * 32u) ^ swz_me);
    const unsigned woff1 = (((unsigned)s_me * 32u + 16u) ^ swz_me);

    const int grp = j >> 4;                    // barrier group (8 groups of 16)

    // bias registers (xp reduction adds these)
    const float bias0 = __ldg(bf + colg), bias1 = __ldg(bi + colg);
    const float bias2 = __ldg(bc + colg), bias3 = __ldg(bo + colg);

    float creg = 0.f;
    unsigned gen = 0;

    const int kb16 = kh * 16;                  // this warp's kk16 range (16 slices)
    const int arow = wm * 16 + gq;             // a-frag row

    float xr[4];

    // ================= xp-GEMM macro body (snext slice of x @ U + bias) =========
    #define XP_GEMM(snext)                                                         \
    {                                                                              \
        const uint2* __restrict__ xb = g_xf + (size_t)(snext) * 16384;             \
        float acc[4][4];                                                           \
        _Pragma("unroll")                                                          \
        for (int g = 0; g < 4; g++)                                                \
            _Pragma("unroll")                                                      \
            for (int p = 0; p < 4; p++) acc[g][p] = 0.f;                           \
        uint2 qA[4][2];                                                            \
        _Pragma("unroll")                                                          \
        for (int p = 0; p < 4; p++) {                                              \
            int base = ((kb16 + p) * 64 + arow) * 4 + tq;                          \
            qA[p][0] = __ldg(xb + base);                                           \
            qA[p][1] = __ldg(xb + base + 32);                                      \
        }                                                                          \
        _Pragma("unroll 4")                                                        \
        for (int i = 0; i < 16; i++) {                                             \
            int sl = i & 3;                                                        \
            uint2 u0 = qA[sl][0], u1 = qA[sl][1];                                  \
            if (i < 12) {                                                          \
                int base = ((kb16 + i + 4) * 64 + arow) * 4 + tq;                  \
                qA[sl][0] = __ldg(xb + base);                                      \
                qA[sl][1] = __ldg(xb + base + 32);                                 \
            }                                                                      \
            unsigned a0[4] = { u0.x, u1.x, u0.y, u1.y };                           \
            unsigned wb = (unsigned)SM_U_BASE + (unsigned)(kb16 + i) * 1024u;      \
            uint4 b01 = *(const uint4*)(sm_raw + wb + woff0);                      \
            uint4 b23 = *(const uint4*)(sm_raw + wb + woff1);                      \
            mma16(acc[0], a0, b01.x, b01.y);                                       \
            mma16(acc[1], a0, b01.z, b01.w);                                       \
            mma16(acc[2], a0, b23.x, b23.y);                                       \
            mma16(acc[3], a0, b23.z, b23.w);                                       \
        }                                                                          \
        float4* dst4 = red4 + (w * 32 + lane) * RED_NP;                            \
        _Pragma("unroll")                                                          \
        for (int p = 0; p < 4; p++)                                                \
            dst4[p] = make_float4(acc[0][p], acc[1][p], acc[2][p], acc[3][p]);     \
        __syncthreads();                                                           \
        float gs0 = 0.f, gs1 = 0.f, gs2 = 0.f, gs3 = 0.f;                          \
        _Pragma("unroll")                                                          \
        for (int kh2 = 0; kh2 < 4; kh2++) {                                        \
            float4 v = red4[((kh2 * 4 + r_wm) * 32 + r_lane) * RED_NP + r_p];      \
            gs0 += v.x; gs1 += v.y; gs2 += v.z; gs3 += v.w;                        \
        }                                                                          \
        xr[0] = gs0 + bias0; xr[1] = gs1 + bias1;                                  \
        xr[2] = gs2 + bias2; xr[3] = gs3 + bias3;                                  \
    }
    // ============================================================================

    // prologue: xp for step 0 (red buffer free after pack sync)
    XP_GEMM(0);
    __syncthreads();    // all threads done reading red before step 0's h dump

    for (int s = 0; s < SS; s++) {
        const uint2* __restrict__ hb = (const uint2*)g_hf[s & 1];
        __half*      __restrict__ hw = (__half*)g_hf[(s + 1) & 1];

        float acc[4][4];
        #pragma unroll
        for (int g = 0; g < 4; g++)
            #pragma unroll
            for (int p = 0; p < 4; p++) acc[g][p] = 0.f;

        // h-GEMM: 4-deep a-fragment prefetch queue
        uint2 qA[4][2];
        #pragma unroll
        for (int p = 0; p < 4; p++) {
            int base = ((kb16 + p) * 64 + arow) * 4 + tq;
            qA[p][0] = __ldcg(hb + base);
            qA[p][1] = __ldcg(hb + base + 32);
        }

        #pragma unroll 4
        for (int i = 0; i < 16; i++) {
            int sl = i & 3;
            uint2 u0 = qA[sl][0], u1 = qA[sl][1];
            if (i < 12) {
                int base = ((kb16 + i + 4) * 64 + arow) * 4 + tq;
                qA[sl][0] = __ldcg(hb + base);
                qA[sl][1] = __ldcg(hb + base + 32);
            }
            unsigned a0[4] = { u0.x, u1.x, u0.y, u1.y };
            unsigned wb = (unsigned)(kb16 + i) * 1024u;
            uint4 b01 = *(const uint4*)(sm_raw + wb + woff0);
            uint4 b23 = *(const uint4*)(sm_raw + wb + woff1);
            mma16(acc[0], a0, b01.x, b01.y);
            mma16(acc[1], a0, b01.z, b01.w);
            mma16(acc[2], a0, b23.x, b23.y);
            mma16(acc[3], a0, b23.z, b23.w);
        }

        // dump h partials (p-major float4, padded stride)
        {
            float4* dst4 = red4 + (w * 32 + lane) * RED_NP;
            #pragma unroll
            for (int p = 0; p < 4; p++)
                dst4[p] = make_float4(acc[0][p], acc[1][p], acc[2][p], acc[3][p]);
        }
        __syncthreads();

        // reduction + gate epilogue
        float hn, cn;
        {
            float gs0 = 0.f, gs1 = 0.f, gs2 = 0.f, gs3 = 0.f;
            #pragma unroll
            for (int kh2 = 0; kh2 < 4; kh2++) {
                float4 v = red4[((kh2 * 4 + r_wm) * 32 + r_lane) * RED_NP + r_p];
                gs0 += v.x; gs1 += v.y; gs2 += v.z; gs3 += v.w;
            }
            float gf = gs0 + xr[0];
            float gi = gs1 + xr[1];
            float gc = gs2 + xr[2];
            float go = gs3 + xr[3];
            cn = sigmf(gf) * creg + sigmf(gi) * tanhf(gc);
            creg = cn;
            hn = sigmf(go) * tanhf(cn);
            st_h_cg(hw + hidx, __float2half_rn(hn));
        }

        // publish h_{s+1}, arrive at barrier as early as possible
        __threadfence();
        __syncthreads();
        gen++;
        if (tid == 0) {
            unsigned t = atomicAdd(&g_cnt1[grp * 32], 1u);
            if (t == gen * 16u - 1u) {
                unsigned r = atomicAdd(&g_cnt2, 1u);
                if (r == gen * 8u - 1u)
                    atomicExch(&g_gen, gen);
            }
        }

        // barrier slack: xp-GEMM for step s+1 (no dependency on peers)
        if (s + 1 < SS) {
            XP_GEMM(s + 1);
        }

        // also in slack: hidden_seq store (+ final outputs)
        out_hs[((size_t)rrow * SS + s) * HH + colg] = hn;
        if (s == SS - 1) {
            out[(size_t)rrow * HH + colg] = hn;
            out[(size_t)BB * HH + (size_t)rrow * HH + colg] = cn;
        }

        if (tid == 0) {
            while (ld_acq(&g_gen) < gen) { }
        }
        __syncthreads();
    }
    #undef XP_GEMM
}

// ---------------- launch ----------------
extern "C" void kernel_launch(void* const* d_in, const int* in_sizes, int n_in,
                              void* d_out, int out_size)
{
    const float* x  = (const float*)d_in[0];
    const float* Uf = (const float*)d_in[1];
    const float* Ui = (const float*)d_in[2];
    const float* Uc = (const float*)d_in[3];
    const float* Uo = (const float*)d_in[4];
    const float* Wf = (const float*)d_in[5];
    const float* Wi = (const float*)d_in[6];
    const float* Wc = (const float*)d_in[7];
    const float* Wo = (const float*)d_in[8];
    const float* bf = (const float*)d_in[9];
    const float* bi = (const float*)d_in[10];
    const float* bc = (const float*)d_in[11];
    const float* bo = (const float*)d_in[12];
    float* out = (float*)d_out;

    static int smem_set = 0;
    if (!smem_set) {
        cudaFuncSetAttribute(lstm_persistent,
                             cudaFuncAttributeMaxDynamicSharedMemorySize, SM_TOTAL);
        smem_set = 1;
    }

    pack_kernel<<<dim3(32, 32, 8), dim3(32, 8)>>>(Uf, Ui, Uc, Uo, Wf, Wi, Wc, Wo);
    xconv_kernel<<<(SS * 16384) / 256, 256>>>(x);     // 2^23 jobs, 1 uint2 each
    init_kernel<<<(32768 + 255) / 256, 256>>>();

    float* hs = out + 2 * BB * HH;   // hidden_seq region
    lstm_persistent<<<NCTA, PTHR, SM_TOTAL>>>(out, hs, bf, bi, bc, bo);
}

// round 14
// speedup vs baseline: 1.8703x; 1.0777x over previous
#include <cuda_runtime.h>
#include <cuda_fp16.h>

#define BB 64
#define SS 512
#define II 1024
#define HH 1024
#define NG 4096          // 4*H
#define MMR (BB*SS)      // 32768
#define NCTA 128
#define PTHR 512

// ---------------- device scratch (no allocs allowed) ----------------
__device__ __align__(16) __half g_Uph[(size_t)NG * II];     // U_all^T [n][k], fp16
__device__ __align__(16) __half g_Wph[(size_t)NG * HH];     // W_all^T [n][k], fp16
// x fp16 in a-fragment order per step: uint2 g_xf[s][ (kk16*64 + row)*4 + tq ]
__device__ __align__(16) uint2 g_xf[(size_t)SS * 16384];
// h fp16 in a-fragment order (same convention), double buffered
__device__ __align__(16) unsigned g_hf[2][32768];
// two-level grid barrier: 8 group counters (128B-strided) -> root -> broadcast gen
__device__ unsigned g_cnt1[8 * 32];
__device__ unsigned g_cnt2;
__device__ unsigned g_gen;

// ---------------- helpers ----------------
__device__ __forceinline__ unsigned h2pack(float lo, float hi) {
    unsigned u;
    asm("cvt.rn.f16x2.f32 %0, %1, %2;" : "=r"(u) : "f"(hi), "f"(lo));
    return u;
}

__device__ __forceinline__ void mma16(float* d, const unsigned* a, unsigned b0, unsigned b1) {
    asm volatile(
        "mma.sync.aligned.m16n8k16.row.col.f32.f16.f16.f32 "
        "{%0,%1,%2,%3}, {%4,%5,%6,%7}, {%8,%9}, {%0,%1,%2,%3};"
        : "+f"(d[0]), "+f"(d[1]), "+f"(d[2]), "+f"(d[3])
        : "r"(a[0]), "r"(a[1]), "r"(a[2]), "r"(a[3]), "r"(b0), "r"(b1));
}

__device__ __forceinline__ float sigmf(float x) { return 1.f / (1.f + __expf(-x)); }

__device__ __forceinline__ void st_h_cg(__half* p, __half v) {
    unsigned short s = __half_as_ushort(v);
    asm volatile("st.global.cg.u16 [%0], %1;" :: "l"(p), "h"(s) : "memory");
}

__device__ __forceinline__ unsigned ld_acq(const unsigned* p) {
    unsigned v;
    asm volatile("ld.acquire.gpu.global.u32 %0, [%1];" : "=r"(v) : "l"(p) : "memory");
    return v;
}

__device__ __forceinline__ unsigned atom_add_acqrel(unsigned* p, unsigned v) {
    unsigned old;
    asm volatile("atom.add.acq_rel.gpu.global.u32 %0, [%1], %2;"
                 : "=r"(old) : "l"(p), "r"(v) : "memory");
    return old;
}

__device__ __forceinline__ void st_rel(unsigned* p, unsigned v) {
    asm volatile("st.release.gpu.global.u32 [%0], %1;" :: "l"(p), "r"(v) : "memory");
}

// ---------------- pack: build K-major fp16 U_all^T / W_all^T ----------------
__global__ void pack_kernel(
    const float* __restrict__ Uf, const float* __restrict__ Ui,
    const float* __restrict__ Uc, const float* __restrict__ Uo,
    const float* __restrict__ Wf, const float* __restrict__ Wi,
    const float* __restrict__ Wc, const float* __restrict__ Wo)
{
    __shared__ float t[32][33];
    int z = blockIdx.z;
    int g = z & 3;
    const float* src;
    __half* dst;
    if (z < 4) { src = (g == 0) ? Uf : (g == 1) ? Ui : (g == 2) ? Uc : Uo; dst = g_Uph; }
    else       { src = (g == 0) ? Wf : (g == 1) ? Wi : (g == 2) ? Wc : Wo; dst = g_Wph; }
    int n0 = blockIdx.x * 32, k0 = blockIdx.y * 32;
    int tx = threadIdx.x, ty = threadIdx.y;   // 32 x 8
    #pragma unroll
    for (int i = 0; i < 4; i++) {
        int kr = ty + i * 8;
        t[kr][tx] = src[(size_t)(k0 + kr) * HH + n0 + tx];
    }
    __syncthreads();
    #pragma unroll
    for (int i = 0; i < 4; i++) {
        int nr = ty + i * 8;
        dst[(size_t)(g * HH + n0 + nr) * II + k0 + tx] = __float2half_rn(t[tx][nr]);
    }
}

// ---------------- x fp32 -> fp16 a-fragment order ----------------
// Job space: SS*16384 = 2^23 jobs, one uint2 each. idx bits: tq(2)|row(6)|kk(6)|s(9)
__global__ void xconv_kernel(const float* __restrict__ x) {
    int idx = blockIdx.x * 256 + threadIdx.x;
    if (idx >= SS * 16384) return;
    int tq  = idx & 3;
    int row = (idx >> 2) & 63;
    int kk  = (idx >> 8) & 63;
    int s   = idx >> 14;
    const float* xr = x + ((size_t)row * SS + s) * II + kk * 16;
    float2 lo = *(const float2*)(xr + 2 * tq);
    float2 hi = *(const float2*)(xr + 2 * tq + 8);
    g_xf[(size_t)s * 16384 + (kk * 64 + row) * 4 + tq] =
        make_uint2(h2pack(lo.x, lo.y), h2pack(hi.x, hi.y));
}

__global__ void init_kernel() {
    int i = blockIdx.x * blockDim.x + threadIdx.x;
    if (i < 32768) g_hf[0][i] = 0u;
    if (i < 8 * 32) g_cnt1[i] = 0u;
    if (i == 0) { g_cnt2 = 0u; g_gen = 0u; }
}

// ---------------- fused persistent kernel ----------------
// 128 CTAs x 512 thr (16 warps = 4 m-slabs(16 rows) x 4 K-splits(256)). CTA j owns
// hidden cols [8j,8j+8). W/U fp16 SMEM (64KB each), swizzled. xp partials for step
// s+1 are computed in barrier slack and CARRIED IN acc REGISTERS into step s+1's
// h-GEMM -> one combined dump+reduce per step. acq_rel barrier chain (no membar).
#define SM_W_BYTES   65536
#define SM_U_BASE    65536
#define RED_BASE     131072
#define RED_NP       5                          // float4 slots per (warp,lane), 1 pad
#define SM_RED_BYTES (PTHR * RED_NP * 16)       // 40960
#define SM_TOTAL     (RED_BASE + SM_RED_BYTES)  // 172032

__global__ __launch_bounds__(PTHR, 1) void lstm_persistent(
    float* __restrict__ out, float* __restrict__ out_hs,
    const float* __restrict__ bf, const float* __restrict__ bi,
    const float* __restrict__ bc, const float* __restrict__ bo)
{
    extern __shared__ __align__(16) unsigned char sm_raw[];
    float4* red4 = (float4*)(sm_raw + RED_BASE);             // [(w*32+lane)][RED_NP]

    const int tid = threadIdx.x;
    const int lane = tid & 31, w = tid >> 5;
    const int wm = w & 3, kh = w >> 2;        // 4 m-slabs x 4 K-splits
    const int gq = lane >> 2, tq = lane & 3;
    const int j = blockIdx.x;

    // ---- one-time: pack W and U slices into swizzled fp16 fragment layout ----
    #pragma unroll
    for (int src = 0; src < 2; src++) {
        const unsigned* Wp_u = (const unsigned*)(src == 0 ? g_Wph : g_Uph);
        unsigned obase = src == 0 ? 0u : (unsigned)SM_U_BASE;
        #pragma unroll
        for (int t = 0; t < 8; t++) {
            int job = tid + t * PTHR;        // 4096 jobs = 64 kk16 x 32 slots x 2 chunks
            int kk = job >> 6;
            int rem = job & 63;
            int s  = rem >> 1, chunk = rem & 1;
            int sgq = s >> 2, stq = s & 3;
            int gp = chunk * 2;
            const unsigned* W0 = Wp_u + (size_t)(gp * 1024 + j * 8 + sgq) * 512;
            const unsigned* W1 = W0 + 1024 * 512;
            unsigned lo0 = W0[kk * 8 + stq], hi0 = W0[kk * 8 + stq + 4];
            unsigned lo1 = W1[kk * 8 + stq], hi1 = W1[kk * 8 + stq + 4];
            unsigned swz = ((unsigned)(s >> 2) & 1u) * 16u;
            unsigned off = obase + (unsigned)kk * 1024u +
                           (((unsigned)s * 32u + (unsigned)chunk * 16u) ^ swz);
            *(uint4*)(sm_raw + off) = make_uint4(lo0, hi0, lo1, hi1);
        }
    }
    __syncthreads();

    // ---- per-thread epilogue mapping (one (row, cc) output per thread) ----
    const int rrow = tid >> 3, cc = tid & 7;
    const int r_wm = rrow >> 4;                              // m-slab (16 rows)
    const int r_p  = ((rrow >> 3) & 1) * 2 + (cc & 1);
    const int r_lane = (rrow & 7) * 4 + (cc >> 1);
    const int colg = j * 8 + cc;
    const int kkj = j >> 1;
    const int hidx = (((kkj * 64 + rrow) * 4 + (cc >> 1)) * 2 + (j & 1)) * 2 + (cc & 1);

    // per-thread b-frag smem offsets (swizzled)
    const int s_me = gq * 4 + tq;
    const unsigned swz_me = ((unsigned)(s_me >> 2) & 1u) * 16u;
    const unsigned woff0 = (((unsigned)s_me * 32u) ^ swz_me);
    const unsigned woff1 = (((unsigned)s_me * 32u + 16u) ^ swz_me);

    const int grp = j >> 4;                    // barrier group (8 groups of 16)

    const float bias0 = __ldg(bf + colg), bias1 = __ldg(bi + colg);
    const float bias2 = __ldg(bc + colg), bias3 = __ldg(bo + colg);

    float creg = 0.f;
    unsigned gen = 0;

    const int kb16 = kh * 16;                  // this warp's kk16 range (16 slices)
    const int arow = wm * 16 + gq;             // a-frag row

    // acc carries xp partials (for the upcoming step) across the barrier, then the
    // h-GEMM accumulates on top -> one combined reduction.
    float acc[4][4];

    // ================= xp-GEMM into acc (registers only, no syncs) ==============
    #define XP_GEMM(snext)                                                         \
    {                                                                              \
        const uint2* __restrict__ xb = g_xf + (size_t)(snext) * 16384;             \
        _Pragma("unroll")                                                          \
        for (int g = 0; g < 4; g++)                                                \
            _Pragma("unroll")                                                      \
            for (int p = 0; p < 4; p++) acc[g][p] = 0.f;                           \
        uint2 qA[4][2];                                                            \
        _Pragma("unroll")                                                          \
        for (int p = 0; p < 4; p++) {                                              \
            int base = ((kb16 + p) * 64 + arow) * 4 + tq;                          \
            qA[p][0] = __ldg(xb + base);                                           \
            qA[p][1] = __ldg(xb + base + 32);                                      \
        }                                                                          \
        _Pragma("unroll 4")                                                        \
        for (int i = 0; i < 16; i++) {                                             \
            int sl = i & 3;                                                        \
            uint2 u0 = qA[sl][0], u1 = qA[sl][1];                                  \
            if (i < 12) {                                                          \
                int base = ((kb16 + i + 4) * 64 + arow) * 4 + tq;                  \
                qA[sl][0] = __ldg(xb + base);                                      \
                qA[sl][1] = __ldg(xb + base + 32);                                 \
            }                                                                      \
            unsigned a0[4] = { u0.x, u1.x, u0.y, u1.y };                           \
            unsigned wb = (unsigned)SM_U_BASE + (unsigned)(kb16 + i) * 1024u;      \
            uint4 b01 = *(const uint4*)(sm_raw + wb + woff0);                      \
            uint4 b23 = *(const uint4*)(sm_raw + wb + woff1);                      \
            mma16(acc[0], a0, b01.x, b01.y);                                       \
            mma16(acc[1], a0, b01.z, b01.w);                                       \
            mma16(acc[2], a0, b23.x, b23.y);                                       \
            mma16(acc[3], a0, b23.z, b23.w);                                       \
        }                                                                          \
    }
    // ============================================================================

    // prologue: xp partials for step 0
    XP_GEMM(0);

    for (int s = 0; s < SS; s++) {
        const uint2* __restrict__ hb = (const uint2*)g_hf[s & 1];
        __half*      __restrict__ hw = (__half*)g_hf[(s + 1) & 1];

        // h-GEMM accumulates onto xp partials already in acc
        uint2 qA[4][2];
        #pragma unroll
        for (int p = 0; p < 4; p++) {
            int base = ((kb16 + p) * 64 + arow) * 4 + tq;
            qA[p][0] = __ldcg(hb + base);
            qA[p][1] = __ldcg(hb + base + 32);
        }

        #pragma unroll 4
        for (int i = 0; i < 16; i++) {
            int sl = i & 3;
            uint2 u0 = qA[sl][0], u1 = qA[sl][1];
            if (i < 12) {
                int base = ((kb16 + i + 4) * 64 + arow) * 4 + tq;
                qA[sl][0] = __ldcg(hb + base);
                qA[sl][1] = __ldcg(hb + base + 32);
            }
            unsigned a0[4] = { u0.x, u1.x, u0.y, u1.y };
            unsigned wb = (unsigned)(kb16 + i) * 1024u;
            uint4 b01 = *(const uint4*)(sm_raw + wb + woff0);
            uint4 b23 = *(const uint4*)(sm_raw + wb + woff1);
            mma16(acc[0], a0, b01.x, b01.y);
            mma16(acc[1], a0, b01.z, b01.w);
            mma16(acc[2], a0, b23.x, b23.y);
            mma16(acc[3], a0, b23.z, b23.w);
        }

        // combined dump (p-major float4, padded stride)
        {
            float4* dst4 = red4 + (w * 32 + lane) * RED_NP;
            #pragma unroll
            for (int p = 0; p < 4; p++)
                dst4[p] = make_float4(acc[0][p], acc[1][p], acc[2][p], acc[3][p]);
        }
        __syncthreads();

        // combined reduction + gate epilogue
        float hn, cn;
        {
            float gs0 = 0.f, gs1 = 0.f, gs2 = 0.f, gs3 = 0.f;
            #pragma unroll
            for (int kh2 = 0; kh2 < 4; kh2++) {
                float4 v = red4[((kh2 * 4 + r_wm) * 32 + r_lane) * RED_NP + r_p];
                gs0 += v.x; gs1 += v.y; gs2 += v.z; gs3 += v.w;
            }
            float gf = gs0 + bias0;
            float gi = gs1 + bias1;
            float gc = gs2 + bias2;
            float go = gs3 + bias3;
            cn = sigmf(gf) * creg + sigmf(gi) * tanhf(gc);
            creg = cn;
            hn = sigmf(go) * tanhf(cn);
            st_h_cg(hw + hidx, __float2half_rn(hn));
        }

        // publish h_{s+1}: syncthreads orders all h stores before tid0's release arrive
        __syncthreads();
        gen++;
        if (tid == 0) {
            unsigned t = atom_add_acqrel(&g_cnt1[grp * 32], 1u);
            if (t == gen * 16u - 1u) {
                unsigned r = atom_add_acqrel(&g_cnt2, 1u);
                if (r == gen * 8u - 1u)
                    st_rel(&g_gen, gen);
            }
        }

        // barrier slack: xp partials for step s+1 (registers only)
        if (s + 1 < SS) {
            XP_GEMM(s + 1);
        }

        // also in slack: hidden_seq store (+ final outputs)
        out_hs[((size_t)rrow * SS + s) * HH + colg] = hn;
        if (s == SS - 1) {
            out[(size_t)rrow * HH + colg] = hn;
            out[(size_t)BB * HH + (size_t)rrow * HH + colg] = cn;
        }

        if (tid == 0) {
            while (ld_acq(&g_gen) < gen) { }
        }
        __syncthreads();
    }
    #undef XP_GEMM
}

// ---------------- launch ----------------
extern "C" void kernel_launch(void* const* d_in, const int* in_sizes, int n_in,
                              void* d_out, int out_size)
{
    const float* x  = (const float*)d_in[0];
    const float* Uf = (const float*)d_in[1];
    const float* Ui = (const float*)d_in[2];
    const float* Uc = (const float*)d_in[3];
    const float* Uo = (const float*)d_in[4];
    const float* Wf = (const float*)d_in[5];
    const float* Wi = (const float*)d_in[6];
    const float* Wc = (const float*)d_in[7];
    const float* Wo = (const float*)d_in[8];
    const float* bf = (const float*)d_in[9];
    const float* bi = (const float*)d_in[10];
    const float* bc = (const float*)d_in[11];
    const float* bo = (const float*)d_in[12];
    float* out = (float*)d_out;

    static int smem_set = 0;
    if (!smem_set) {
        cudaFuncSetAttribute(lstm_persistent,
                             cudaFuncAttributeMaxDynamicSharedMemorySize, SM_TOTAL);
        smem_set = 1;
    }

    pack_kernel<<<dim3(32, 32, 8), dim3(32, 8)>>>(Uf, Ui, Uc, Uo, Wf, Wi, Wc, Wo);
    xconv_kernel<<<(SS * 16384) / 256, 256>>>(x);     // 2^23 jobs, 1 uint2 each
    init_kernel<<<(32768 + 255) / 256, 256>>>();

    float* hs = out + 2 * BB * HH;   // hidden_seq region
    lstm_persistent<<<NCTA, PTHR, SM_TOTAL>>>(out, hs, bf, bi, bc, bo);
}